// round 1
// baseline (speedup 1.0000x reference)
#include <cuda_runtime.h>
#include <math.h>

#define T_   8
#define NV   8192
#define EE   131072
#define HH   8
#define CC   100
#define DG   128
#define DHD  16
#define DAGG 384
#define DR   256
#define DD1  128
#define DD2  64

// ---------------- scratch layout (floats) ----------------
constexpr long OFF_H    = 0;                                   // [T*NV*DG]  h = xW
constexpr long OFF_X    = OFF_H    + (long)T_*NV*DG;           // [T*NV*DG]  gat layer output
constexpr long OFF_SS   = OFF_X    + (long)T_*NV*DG;           // [T*NV*HH]
constexpr long OFF_SD   = OFF_SS   + (long)T_*NV*HH;
constexpr long OFF_E    = OFF_SD   + (long)T_*NV*HH;           // [T*EE*HH] edge scores / ex
constexpr long OFF_M    = OFF_E    + (long)T_*EE*HH;           // [T*NV*HH] segment max
constexpr long OFF_DN   = OFF_M    + (long)T_*NV*HH;           // [T*NV*HH] denom
constexpr long OFF_O    = OFF_DN   + (long)T_*NV*HH;           // [T*NV*DG] atomic agg
constexpr long OFF_NUM  = OFF_O    + (long)T_*NV*DG;           // [T*CC*DG]
constexpr long OFF_CD   = OFF_NUM  + (long)T_*CC*DG;           // [T*CC]
constexpr long OFF_MES  = OFF_CD   + (long)T_*CC;              // [T*CC*DG]
constexpr long OFF_MAC  = OFF_MES  + (long)T_*CC*DG;           // [T*DG]
constexpr long OFF_AGG  = OFF_MAC  + (long)T_*DG;              // [T*NV*DAGG]
constexpr long OFF_Z    = OFF_AGG  + (long)T_*NV*DAGG;         // [NV*4*DR]
constexpr long OFF_HS   = OFF_Z    + (long)NV*4*DR;            // [NV*DR]
constexpr long OFF_CS   = OFF_HS   + (long)NV*DR;              // [NV*DR]
constexpr long OFF_E1   = OFF_CS   + (long)NV*DR;              // [NV*DD1]
constexpr long OFF_EMB  = OFF_E1   + (long)NV*DD1;             // [NV*DD2]
constexpr long OFF_EMBN = OFF_EMB  + (long)NV*DD2;             // [NV*DD2]
constexpr long OFF_S1   = OFF_EMBN + (long)NV*DD2;             // [NV*DD1]
constexpr long OFF_SC   = OFF_S1   + (long)NV*DD1;             // [NV*DD2]
constexpr long OFF_SQ   = OFF_SC   + (long)NV*DD2;             // [NV]
constexpr long OFF_CNI  = OFF_SQ   + (long)NV;                 // [DD2]
constexpr long TOTAL    = OFF_CNI  + (long)DD2;

__device__ float g_buf[TOTAL];

// ---------------- helpers ----------------
__device__ __forceinline__ float sigmoidf_(float x){ return 1.f/(1.f+expf(-x)); }

__device__ __forceinline__ void atomicMaxF(float* addr, float v){
    if (v >= 0.f) atomicMax((int*)addr, __float_as_int(v));
    else          atomicMin((unsigned int*)addr, __float_as_uint(v));
}

__global__ void fillk(float* p, long n, float v){
    long i = (long)blockIdx.x*blockDim.x + threadIdx.x;
    if (i < n) p[i] = v;
}

__global__ void copyk(const float* __restrict__ a, float* __restrict__ b, long n){
    long i = (long)blockIdx.x*blockDim.x + threadIdx.x;
    if (i < n) b[i] = a[i];
}

// ---------------- SGEMM: C = [acc?C:0] + A[MxK] @ B[KxN] (+bias) ----------------
// BM=BN=128, BK=16, 256 threads, 8x8 per thread. Requires M%128==0, N%128==0, K%16==0.
__global__ void __launch_bounds__(256) sgemm_k(
    const float* __restrict__ A, const float* __restrict__ B,
    const float* __restrict__ bias, float* __restrict__ Cm,
    int M, int Nn, int K, int accFlag)
{
    __shared__ float As[16][128];
    __shared__ float Bs[16][132];
    int bx = blockIdx.x, by = blockIdx.y;
    int tid = threadIdx.x;
    int tx = tid & 15, ty = tid >> 4;

    float acc[8][8];
    #pragma unroll
    for (int i=0;i<8;i++)
        #pragma unroll
        for (int j=0;j<8;j++) acc[i][j] = 0.f;

    int ar = tid >> 2;          // 0..63
    int ak = (tid & 3) * 4;     // 0,4,8,12
    int br = tid >> 5;          // 0..7
    int bc = (tid & 31) * 4;    // 0..124

    for (int k0 = 0; k0 < K; k0 += 16){
        #pragma unroll
        for (int i=0;i<2;i++){
            int row = ar + i*64;
            float4 v = *(const float4*)(A + (long)(by*128 + row)*K + k0 + ak);
            As[ak+0][row]=v.x; As[ak+1][row]=v.y; As[ak+2][row]=v.z; As[ak+3][row]=v.w;
        }
        #pragma unroll
        for (int i=0;i<2;i++){
            int r = br + i*8;
            float4 v = *(const float4*)(B + (long)(k0 + r)*Nn + bx*128 + bc);
            *(float4*)&Bs[r][bc] = v;
        }
        __syncthreads();
        #pragma unroll
        for (int k=0;k<16;k++){
            float4 a0 = *(float4*)&As[k][ty*8];
            float4 a1 = *(float4*)&As[k][ty*8+4];
            float4 b0 = *(float4*)&Bs[k][tx*8];
            float4 b1 = *(float4*)&Bs[k][tx*8+4];
            float ra[8] = {a0.x,a0.y,a0.z,a0.w,a1.x,a1.y,a1.z,a1.w};
            float rb[8] = {b0.x,b0.y,b0.z,b0.w,b1.x,b1.y,b1.z,b1.w};
            #pragma unroll
            for (int i=0;i<8;i++)
                #pragma unroll
                for (int j=0;j<8;j++) acc[i][j] += ra[i]*rb[j];
        }
        __syncthreads();
    }

    #pragma unroll
    for (int i=0;i<8;i++){
        long row = (long)by*128 + ty*8 + i;
        #pragma unroll
        for (int jj=0;jj<8;jj+=4){
            int col = bx*128 + tx*8 + jj;
            float4 v = make_float4(acc[i][jj],acc[i][jj+1],acc[i][jj+2],acc[i][jj+3]);
            if (bias){
                float4 bb = *(const float4*)(bias + col);
                v.x+=bb.x; v.y+=bb.y; v.z+=bb.z; v.w+=bb.w;
            }
            if (accFlag){
                float4 o = *(float4*)(Cm + row*Nn + col);
                v.x+=o.x; v.y+=o.y; v.z+=o.z; v.w+=o.w;
            }
            *(float4*)(Cm + row*Nn + col) = v;
        }
    }
}

// ---------------- small gemm + activation (act 0=none,1=tanh,2=sigmoid) ----------------
__global__ void small_gemm(const float* __restrict__ A, const float* __restrict__ B,
                           const float* __restrict__ bias, float* __restrict__ Cm,
                           int M, int Nn, int K, int act)
{
    long idx = (long)blockIdx.x*blockDim.x + threadIdx.x;
    if (idx >= (long)M*Nn) return;
    int col = (int)(idx % Nn);
    long row = idx / Nn;
    float acc = bias ? bias[col] : 0.f;
    const float* a = A + row*K;
    #pragma unroll 8
    for (int k=0;k<K;k++) acc += a[k]*__ldg(&B[(long)k*Nn+col]);
    if (act==1) acc = tanhf(acc);
    else if (act==2) acc = sigmoidf_(acc);
    Cm[idx] = acc;
}

// ---------------- GAT ----------------
__global__ void gat_scores(const float* __restrict__ h, const float* __restrict__ asrc,
                           const float* __restrict__ adst, float* __restrict__ ss,
                           float* __restrict__ sd)
{
    int idx = blockIdx.x*blockDim.x + threadIdx.x;   // T*NV*HH
    if (idx >= T_*NV*HH) return;
    int hh = idx % HH;
    long node = idx / HH;
    const float* hp = h + node*DG + hh*DHD;
    float a = 0.f, b = 0.f;
    #pragma unroll
    for (int d=0; d<DHD; d++){
        float v = hp[d];
        a += v*asrc[hh*DHD+d];
        b += v*adst[hh*DHD+d];
    }
    ss[idx] = a; sd[idx] = b;
}

__global__ void edge_score_max(const int* __restrict__ ei, const float* __restrict__ ew,
                               const float* __restrict__ ss, const float* __restrict__ sd,
                               float* __restrict__ esc, float* __restrict__ m)
{
    long idx = (long)blockIdx.x*blockDim.x + threadIdx.x;   // T*EE*HH
    if (idx >= (long)T_*EE*HH) return;
    int hh = (int)(idx % HH);
    long te = idx / HH;
    int e = (int)(te % EE);
    int t = (int)(te / EE);
    int src = ei[(long)t*2*EE + e];
    int dst = ei[(long)t*2*EE + EE + e];
    float s = ss[((long)t*NV+src)*HH+hh] + sd[((long)t*NV+dst)*HH+hh];
    s = (s > 0.f) ? s : 0.2f*s;
    s *= ew[(long)t*EE + e];
    esc[idx] = s;
    atomicMaxF(&m[((long)t*NV+dst)*HH+hh], s);
}

__global__ void edge_exp_sum(const int* __restrict__ ei, const float* __restrict__ m,
                             float* __restrict__ esc, float* __restrict__ dn)
{
    long idx = (long)blockIdx.x*blockDim.x + threadIdx.x;   // T*EE*HH
    if (idx >= (long)T_*EE*HH) return;
    int hh = (int)(idx % HH);
    long te = idx / HH;
    int e = (int)(te % EE);
    int t = (int)(te / EE);
    int dst = ei[(long)t*2*EE + EE + e];
    float ex = expf(esc[idx] - m[((long)t*NV+dst)*HH+hh]);
    esc[idx] = ex;
    atomicAdd(&dn[((long)t*NV+dst)*HH+hh], ex);
}

__global__ void edge_agg(const int* __restrict__ ei, const float* __restrict__ esc,
                         const float* __restrict__ dn, const float* __restrict__ h,
                         float* __restrict__ out)
{
    long gtid = (long)blockIdx.x*blockDim.x + threadIdx.x;
    long wid = gtid >> 5;
    int lane = (int)(gtid & 31);
    if (wid >= (long)T_*EE) return;
    int e = (int)(wid % EE);
    int t = (int)(wid / EE);
    int src = ei[(long)t*2*EE + e];
    int dst = ei[(long)t*2*EE + EE + e];
    int hh = lane >> 2;
    float ex  = esc[((long)t*EE+e)*HH + hh];
    float den = dn[((long)t*NV+dst)*HH + hh];
    float alpha = ex / (den + 1e-16f);
    float4 hv = *(const float4*)(h + ((long)t*NV+src)*DG + lane*4);
    float* op = out + ((long)t*NV+dst)*DG + lane*4;
    atomicAdd(op+0, alpha*hv.x);
    atomicAdd(op+1, alpha*hv.y);
    atomicAdd(op+2, alpha*hv.z);
    atomicAdd(op+3, alpha*hv.w);
}

__global__ void elu_k(const float* __restrict__ in, float* __restrict__ o, long n){
    long i = (long)blockIdx.x*blockDim.x + threadIdx.x;
    if (i >= n) return;
    float v = in[i];
    o[i] = (v > 0.f) ? v : expm1f(v);
}

// ---------------- fuse ----------------
__global__ void fuse_pool(const float* __restrict__ x, const int* __restrict__ com,
                          const float* __restrict__ w, float* __restrict__ num,
                          float* __restrict__ cd)
{
    long idx = (long)blockIdx.x*blockDim.x + threadIdx.x;   // T*NV*DG
    if (idx >= (long)T_*NV*DG) return;
    int d = (int)(idx % DG);
    long tn = idx / DG;
    int t = (int)(tn / NV);
    int c = com[tn];
    float wv = w[tn];
    atomicAdd(&num[((long)t*CC+c)*DG + d], wv * x[idx]);
    if (d == 0) atomicAdd(&cd[(long)t*CC + c], wv);
}

__global__ void fuse_finalize(const float* __restrict__ num, const float* __restrict__ cd,
                              float* __restrict__ meso, float* __restrict__ mac)
{
    int t = blockIdx.x;
    int d = threadIdx.x;   // 128
    float macn = 0.f, ws = 0.f;
    for (int c=0;c<CC;c++){
        float nv = num[((long)t*CC+c)*DG + d];
        float dv = cd[(long)t*CC + c];
        meso[((long)t*CC+c)*DG + d] = nv/(dv + 1e-16f);
        macn += nv; ws += dv;
    }
    mac[(long)t*DG + d] = macn/(ws + 1e-16f);
}

__global__ void fuse_mix(const float* __restrict__ x, const int* __restrict__ com,
                         const float* __restrict__ meso, const float* __restrict__ mac,
                         float* __restrict__ agg)
{
    long gtid = (long)blockIdx.x*blockDim.x + threadIdx.x;
    long wid = gtid >> 5;
    int lane = (int)(gtid & 31);
    if (wid >= (long)T_*NV) return;
    long tn = wid;
    int t = (int)(tn / NV);
    int c = com[tn];
    float4 mi = *(const float4*)(x + tn*DG + lane*4);
    float4 me = *(const float4*)(meso + ((long)t*CC+c)*DG + lane*4);
    float4 ma = *(const float4*)(mac + (long)t*DG + lane*4);
    float s0 = mi.x+mi.y+mi.z+mi.w;
    float s1 = me.x+me.y+me.z+me.w;
    float s2 = ma.x+ma.y+ma.z+ma.w;
    #pragma unroll
    for (int o=16;o>0;o>>=1){
        s0 += __shfl_xor_sync(0xffffffffu, s0, o);
        s1 += __shfl_xor_sync(0xffffffffu, s1, o);
        s2 += __shfl_xor_sync(0xffffffffu, s2, o);
    }
    s0 *= (1.f/DG); s1 *= (1.f/DG); s2 *= (1.f/DG);
    s0 = (s0>0.f)?s0:0.2f*s0;
    s1 = (s1>0.f)?s1:0.2f*s1;
    s2 = (s2>0.f)?s2:0.2f*s2;
    float mx = fmaxf(s0, fmaxf(s1, s2));
    float e0 = expf(s0-mx), e1 = expf(s1-mx), e2 = expf(s2-mx);
    float inv = 1.f/(e0+e1+e2);
    float a0 = e0*inv, a1 = e1*inv, a2 = e2*inv;
    float* ap = agg + tn*DAGG + lane*4;
    *(float4*)(ap)        = make_float4(a0*mi.x, a0*mi.y, a0*mi.z, a0*mi.w);
    *(float4*)(ap + DG)   = make_float4(a1*me.x, a1*me.y, a1*me.z, a1*me.w);
    *(float4*)(ap + 2*DG) = make_float4(a2*ma.x, a2*ma.y, a2*ma.z, a2*ma.w);
}

// ---------------- LSTM ----------------
__global__ void lstm_gate(const float* __restrict__ z, float* __restrict__ hs,
                          float* __restrict__ cs)
{
    long idx = (long)blockIdx.x*blockDim.x + threadIdx.x;
    if (idx >= (long)NV*DR) return;
    long n = idx / DR;
    int j = (int)(idx % DR);
    const float* zp = z + n*4*DR;
    float zi = zp[j], zf = zp[DR+j], zg = zp[2*DR+j], zo = zp[3*DR+j];
    float c = sigmoidf_(zf)*cs[idx] + sigmoidf_(zi)*tanhf(zg);
    cs[idx] = c;
    hs[idx] = sigmoidf_(zo)*tanhf(c);
}

// ---------------- decoder normalization ----------------
__global__ void colnorm_k(const float* __restrict__ emb, float* __restrict__ cni){
    int col = blockIdx.x;   // 64
    __shared__ float red[256];
    float s = 0.f;
    for (int n = threadIdx.x; n < NV; n += 256){
        float v = emb[(long)n*DD2 + col];
        s += v*v;
    }
    red[threadIdx.x] = s;
    __syncthreads();
    for (int o=128;o>0;o>>=1){
        if (threadIdx.x < o) red[threadIdx.x] += red[threadIdx.x+o];
        __syncthreads();
    }
    if (threadIdx.x == 0) cni[col] = 1.f / fmaxf(sqrtf(red[0]), 1e-12f);
}

__global__ void norm_sq(const float* __restrict__ emb, const float* __restrict__ cni,
                        float* __restrict__ embn, float* __restrict__ sq)
{
    long gtid = (long)blockIdx.x*blockDim.x + threadIdx.x;
    long row = gtid >> 5;
    int lane = (int)(gtid & 31);
    if (row >= NV) return;
    float a = emb[row*DD2 + lane]      * cni[lane];
    float b = emb[row*DD2 + 32 + lane] * cni[32 + lane];
    embn[row*DD2 + lane] = a;
    embn[row*DD2 + 32 + lane] = b;
    float s = a*a + b*b;
    #pragma unroll
    for (int o=16;o>0;o>>=1) s += __shfl_xor_sync(0xffffffffu, s, o);
    if (lane == 0) sq[row] = s;
}

// ---------------- adjacency ----------------
__global__ void __launch_bounds__(256) adj_k(const float* __restrict__ embn,
                                             const float* __restrict__ scal,
                                             const float* __restrict__ sq,
                                             float* __restrict__ out)
{
    extern __shared__ float sm[];
    const int LD = 68;
    float* eI = sm;
    float* eJ = eI + 64*LD;
    float* sI = eJ + 64*LD;
    float* sJ = sI + 64*LD;
    float* sqI = sJ + 64*LD;
    float* sqJ = sqI + 64;

    int bi = blockIdx.y, bj = blockIdx.x;
    int tid = threadIdx.x;

    for (int i = tid; i < 64*16; i += 256){
        int r  = i >> 4;
        int k4 = (i & 15) * 4;
        float4 v;
        v = *(const float4*)(embn + ((long)(bi*64+r))*DD2 + k4);
        eI[(k4+0)*LD+r]=v.x; eI[(k4+1)*LD+r]=v.y; eI[(k4+2)*LD+r]=v.z; eI[(k4+3)*LD+r]=v.w;
        v = *(const float4*)(embn + ((long)(bj*64+r))*DD2 + k4);
        eJ[(k4+0)*LD+r]=v.x; eJ[(k4+1)*LD+r]=v.y; eJ[(k4+2)*LD+r]=v.z; eJ[(k4+3)*LD+r]=v.w;
        v = *(const float4*)(scal + ((long)(bi*64+r))*DD2 + k4);
        sI[(k4+0)*LD+r]=v.x; sI[(k4+1)*LD+r]=v.y; sI[(k4+2)*LD+r]=v.z; sI[(k4+3)*LD+r]=v.w;
        v = *(const float4*)(scal + ((long)(bj*64+r))*DD2 + k4);
        sJ[(k4+0)*LD+r]=v.x; sJ[(k4+1)*LD+r]=v.y; sJ[(k4+2)*LD+r]=v.z; sJ[(k4+3)*LD+r]=v.w;
    }
    if (tid < 64){ sqI[tid] = sq[bi*64+tid]; sqJ[tid] = sq[bj*64+tid]; }
    __syncthreads();

    int ti = tid >> 4, tj = tid & 15;
    int i0 = ti*4, j0 = tj*4;
    float dac[4][4] = {};
    float sac[4][4] = {};
    #pragma unroll 4
    for (int k=0;k<64;k++){
        float4 va  = *(float4*)&eI[k*LD + i0];
        float4 vb  = *(float4*)&eJ[k*LD + j0];
        float4 vsa = *(float4*)&sI[k*LD + i0];
        float4 vsb = *(float4*)&sJ[k*LD + j0];
        float A_[4]  = {va.x,va.y,va.z,va.w};
        float B_[4]  = {vb.x,vb.y,vb.z,vb.w};
        float SA_[4] = {vsa.x,vsa.y,vsa.z,vsa.w};
        float SB_[4] = {vsb.x,vsb.y,vsb.z,vsb.w};
        #pragma unroll
        for (int r=0;r<4;r++)
            #pragma unroll
            for (int c=0;c<4;c++){
                dac[r][c] += A_[r]*B_[c];
                sac[r][c] += SA_[r]*SB_[c];
            }
    }

    #pragma unroll
    for (int r=0;r<4;r++){
        long row = (long)(bi*64 + i0 + r);
        float si = sqI[i0+r];
        float4 o;
        float d0 = si + sqJ[j0+0] - 2.f*dac[r][0];
        float d1 = si + sqJ[j0+1] - 2.f*dac[r][1];
        float d2 = si + sqJ[j0+2] - 2.f*dac[r][2];
        float d3 = si + sqJ[j0+3] - 2.f*dac[r][3];
        o.x = 1.f + tanhf(-d0*sac[r][0]);
        o.y = 1.f + tanhf(-d1*sac[r][1]);
        o.z = 1.f + tanhf(-d2*sac[r][2]);
        o.w = 1.f + tanhf(-d3*sac[r][3]);
        *(float4*)(out + row*NV + bj*64 + j0) = o;
    }
}

// ---------------- launch ----------------
static inline unsigned nb(long n, int b){ return (unsigned)((n + b - 1) / b); }

extern "C" void kernel_launch(void* const* d_in, const int* in_sizes, int n_in,
                              void* d_out, int out_size)
{
    (void)in_sizes; (void)n_in; (void)out_size;
    const int*   ei   = (const int*)  d_in[0];
    const float* ew   = (const float*)d_in[1];
    const float* feat = (const float*)d_in[2];
    const int*   com  = (const int*)  d_in[3];
    const float* nw   = (const float*)d_in[4];
    const float* gatW = (const float*)d_in[5];
    const float* asrc = (const float*)d_in[6];
    const float* adst = (const float*)d_in[7];
    const float* lWx  = (const float*)d_in[8];
    const float* lWh  = (const float*)d_in[9];
    const float* lb   = (const float*)d_in[10];
    const float* eW0  = (const float*)d_in[11];
    const float* eb0  = (const float*)d_in[12];
    const float* eW1  = (const float*)d_in[13];
    const float* eb1  = (const float*)d_in[14];
    const float* sW0  = (const float*)d_in[15];
    const float* sb0  = (const float*)d_in[16];
    const float* sW1  = (const float*)d_in[17];
    const float* sb1  = (const float*)d_in[18];
    float* out = (float*)d_out;

    float* buf = nullptr;
    cudaGetSymbolAddress((void**)&buf, g_buf);
    float* bH   = buf + OFF_H;
    float* bX   = buf + OFF_X;
    float* bSS  = buf + OFF_SS;
    float* bSD  = buf + OFF_SD;
    float* bE   = buf + OFF_E;
    float* bM   = buf + OFF_M;
    float* bDN  = buf + OFF_DN;
    float* bO   = buf + OFF_O;
    float* bNUM = buf + OFF_NUM;
    float* bCD  = buf + OFF_CD;
    float* bMES = buf + OFF_MES;
    float* bMAC = buf + OFF_MAC;
    float* bAGG = buf + OFF_AGG;
    float* bZ   = buf + OFF_Z;
    float* bHS  = buf + OFF_HS;
    float* bCS  = buf + OFF_CS;
    float* bE1  = buf + OFF_E1;
    float* bEMB = buf + OFF_EMB;
    float* bEMBN= buf + OFF_EMBN;
    float* bS1  = buf + OFF_S1;
    float* bSC  = buf + OFF_SC;
    float* bSQ  = buf + OFF_SQ;
    float* bCNI = buf + OFF_CNI;

    // -------- GAT layers --------
    const float* xin = feat;
    for (int l = 0; l < 2; l++){
        sgemm_k<<<dim3(1, (T_*NV)/128), 256>>>(xin, gatW + (long)l*DG*DG, nullptr, bH,
                                               T_*NV, DG, DG, 0);
        gat_scores<<<nb((long)T_*NV*HH, 256), 256>>>(bH, asrc + l*HH*DHD, adst + l*HH*DHD,
                                                     bSS, bSD);
        fillk<<<nb((long)T_*NV*HH, 256), 256>>>(bM,  (long)T_*NV*HH, -INFINITY);
        fillk<<<nb((long)T_*NV*HH, 256), 256>>>(bDN, (long)T_*NV*HH, 0.f);
        fillk<<<nb((long)T_*NV*DG, 256), 256>>>(bO,  (long)T_*NV*DG, 0.f);
        edge_score_max<<<nb((long)T_*EE*HH, 256), 256>>>(ei, ew, bSS, bSD, bE, bM);
        edge_exp_sum<<<nb((long)T_*EE*HH, 256), 256>>>(ei, bM, bE, bDN);
        edge_agg<<<nb((long)T_*EE*32, 256), 256>>>(ei, bE, bDN, bH, bO);
        elu_k<<<nb((long)T_*NV*DG, 256), 256>>>(bO, bX, (long)T_*NV*DG);
        xin = bX;
    }

    // -------- hierarchical fuse --------
    fillk<<<nb((long)T_*CC*DG, 256), 256>>>(bNUM, (long)T_*CC*DG, 0.f);
    fillk<<<nb((long)T_*CC, 256), 256>>>(bCD, (long)T_*CC, 0.f);
    fuse_pool<<<nb((long)T_*NV*DG, 256), 256>>>(bX, com, nw, bNUM, bCD);
    fuse_finalize<<<T_, 128>>>(bNUM, bCD, bMES, bMAC);
    fuse_mix<<<nb((long)T_*NV*32, 256), 256>>>(bX, com, bMES, bMAC, bAGG);

    // -------- LSTM --------
    fillk<<<nb((long)NV*DR, 256), 256>>>(bHS, (long)NV*DR, 0.f);
    fillk<<<nb((long)NV*DR, 256), 256>>>(bCS, (long)NV*DR, 0.f);
    for (int t = 0; t < T_; t++){
        sgemm_k<<<dim3(8, 64), 256>>>(bAGG + (long)t*NV*DAGG, lWx, lb, bZ,
                                      NV, 4*DR, DAGG, 0);
        sgemm_k<<<dim3(8, 64), 256>>>(bHS, lWh, nullptr, bZ, NV, 4*DR, DR, 1);
        lstm_gate<<<nb((long)NV*DR, 256), 256>>>(bZ, bHS, bCS);
    }

    // -------- decoders --------
    small_gemm<<<nb((long)NV*DD1, 256), 256>>>(bHS, eW0, eb0, bE1, NV, DD1, DR, 1);
    small_gemm<<<nb((long)NV*DD2, 256), 256>>>(bE1, eW1, eb1, bEMB, NV, DD2, DD1, 1);
    small_gemm<<<nb((long)NV*DD1, 256), 256>>>(bHS, sW0, sb0, bS1, NV, DD1, DR, 2);
    small_gemm<<<nb((long)NV*DD2, 256), 256>>>(bS1, sW1, sb1, bSC, NV, DD2, DD1, 2);

    colnorm_k<<<DD2, 256>>>(bEMB, bCNI);
    norm_sq<<<nb((long)NV*32, 256), 256>>>(bEMB, bCNI, bEMBN, bSQ);

    // -------- adjacency + emb output --------
    static const int adj_smem = (4*64*68 + 128) * (int)sizeof(float);
    cudaFuncSetAttribute(adj_k, cudaFuncAttributeMaxDynamicSharedMemorySize, adj_smem);
    adj_k<<<dim3(NV/64, NV/64), 256, adj_smem>>>(bEMBN, bSC, bSQ, out);
    copyk<<<nb((long)NV*DD2, 256), 256>>>(bEMB, out + (long)NV*NV, (long)NV*DD2);
}

// round 2
// speedup vs baseline: 1.4822x; 1.4822x over previous
#include <cuda_runtime.h>
#include <math.h>

#define T_   8
#define NV   8192
#define EE   131072
#define HH   8
#define CC   100
#define DG   128
#define DHD  16
#define DAGG 384
#define DR   256
#define DD1  128
#define DD2  64

// ---------------- scratch layout (floats) ----------------
constexpr long OFF_H    = 0;                                   // [T*NV*DG]
constexpr long OFF_X    = OFF_H    + (long)T_*NV*DG;           // [T*NV*DG]
constexpr long OFF_SS   = OFF_X    + (long)T_*NV*DG;           // [T*NV*HH]
constexpr long OFF_SD   = OFF_SS   + (long)T_*NV*HH;
constexpr long OFF_E    = OFF_SD   + (long)T_*NV*HH;           // [T*EE*HH]
constexpr long OFF_M    = OFF_E    + (long)T_*EE*HH;           // [T*NV*HH]
constexpr long OFF_DN   = OFF_M    + (long)T_*NV*HH;           // [T*NV*HH]
constexpr long OFF_O    = OFF_DN   + (long)T_*NV*HH;           // [T*NV*DG]
constexpr long OFF_NUM  = OFF_O    + (long)T_*NV*DG;           // [T*CC*DG]
constexpr long OFF_CD   = OFF_NUM  + (long)T_*CC*DG;           // [T*CC]
constexpr long OFF_MES  = OFF_CD   + (long)T_*CC;              // [T*CC*DG]
constexpr long OFF_MAC  = OFF_MES  + (long)T_*CC*DG;           // [T*DG]
constexpr long OFF_AGG  = OFF_MAC  + (long)T_*DG;              // [T*NV*DAGG]
constexpr long OFF_ZX   = OFF_AGG  + (long)T_*NV*DAGG;         // [T*NV*4*DR]
constexpr long OFF_HS   = OFF_ZX   + (long)T_*NV*4*DR;         // [NV*DR]
constexpr long OFF_CS   = OFF_HS   + (long)NV*DR;              // [NV*DR]
constexpr long OFF_E1   = OFF_CS   + (long)NV*DR;              // [NV*DD1]
constexpr long OFF_EMB  = OFF_E1   + (long)NV*DD1;             // [NV*DD2]
constexpr long OFF_EMBN = OFF_EMB  + (long)NV*DD2;             // [NV*DD2]
constexpr long OFF_S1   = OFF_EMBN + (long)NV*DD2;             // [NV*DD1]
constexpr long OFF_SC   = OFF_S1   + (long)NV*DD1;             // [NV*DD2]
constexpr long OFF_SQ   = OFF_SC   + (long)NV*DD2;             // [NV]
constexpr long OFF_CNI  = OFF_SQ   + (long)NV;                 // [DD2]
constexpr long TOTAL    = OFF_CNI  + (long)DD2;

__device__ float g_buf[TOTAL];

// ---------------- helpers ----------------
__device__ __forceinline__ float sigmoidf_(float x){ return 1.f/(1.f+expf(-x)); }

__device__ __forceinline__ void atomicMaxF(float* addr, float v){
    if (v >= 0.f) atomicMax((int*)addr, __float_as_int(v));
    else          atomicMin((unsigned int*)addr, __float_as_uint(v));
}

__device__ __forceinline__ unsigned f2tf(float x){
    unsigned r; asm("cvt.rna.tf32.f32 %0, %1;" : "=r"(r) : "f"(x)); return r;
}

__device__ __forceinline__ void mma_tf32(float* c, const unsigned* a, const unsigned* b){
    asm volatile("mma.sync.aligned.m16n8k8.row.col.f32.tf32.tf32.f32 "
        "{%0,%1,%2,%3}, {%4,%5,%6,%7}, {%8,%9}, {%0,%1,%2,%3};"
        : "+f"(c[0]),"+f"(c[1]),"+f"(c[2]),"+f"(c[3])
        : "r"(a[0]),"r"(a[1]),"r"(a[2]),"r"(a[3]), "r"(b[0]),"r"(b[1]));
}

__global__ void fillk(float* p, long n, float v){
    long i = (long)blockIdx.x*blockDim.x + threadIdx.x;
    if (i < n) p[i] = v;
}

__global__ void copyk(const float* __restrict__ a, float* __restrict__ b, long n){
    long i = (long)blockIdx.x*blockDim.x + threadIdx.x;
    if (i < n) b[i] = a[i];
}

// ---------------- tf32 tensor-core GEMM ----------------
// C[M,N] = (acc?C:0) + A[MxK]@B[KxN] (+bias) (+act). M%128==0, N%128==0, K%32==0.
// block 256 thr = 8 warps (4x2), block tile 128x128x32, warp tile 32x64.
#define APAD 36
#define BPAD 136
__global__ void __launch_bounds__(256) gemm_tf32(
    const float* __restrict__ A, const float* __restrict__ B,
    const float* __restrict__ bias, float* __restrict__ Cm,
    int M, int Nn, int K, int accFlag, int act)
{
    __shared__ unsigned As[128*APAD];
    __shared__ unsigned Bs[32*BPAD];
    const int bx = blockIdx.x, by = blockIdx.y, tid = threadIdx.x;
    const int wid = tid >> 5, lane = tid & 31;
    const int wm = wid >> 1, wn = wid & 1;
    const int gID = lane >> 2, tig = lane & 3;

    float c[2][8][4];
    #pragma unroll
    for (int i=0;i<2;i++)
        #pragma unroll
        for (int j=0;j<8;j++)
            #pragma unroll
            for (int q=0;q<4;q++) c[i][j][q] = 0.f;

    const int am = tid >> 3;          // 0..31 (base row, 4 chunks of 32)
    const int akq = (tid & 7) * 4;    // 0..28
    const int bk = tid >> 3;          // 0..31
    const int bn = (tid & 7) * 4;     // 0..28, +q*32

    for (int k0 = 0; k0 < K; k0 += 32){
        #pragma unroll
        for (int r = 0; r < 4; r++){
            int m = am + r*32;
            float4 v = *(const float4*)(A + (long)(by*128 + m)*K + k0 + akq);
            unsigned* p = &As[m*APAD + akq];
            p[0]=f2tf(v.x); p[1]=f2tf(v.y); p[2]=f2tf(v.z); p[3]=f2tf(v.w);
        }
        #pragma unroll
        for (int q = 0; q < 4; q++){
            int n = bn + q*32;
            float4 v = *(const float4*)(B + (long)(k0 + bk)*Nn + bx*128 + n);
            unsigned* p = &Bs[bk*BPAD + n];
            p[0]=f2tf(v.x); p[1]=f2tf(v.y); p[2]=f2tf(v.z); p[3]=f2tf(v.w);
        }
        __syncthreads();

        #pragma unroll
        for (int ks = 0; ks < 4; ks++){
            const int k = ks*8;
            unsigned a[2][4];
            #pragma unroll
            for (int mf=0; mf<2; mf++){
                int bm = wm*32 + mf*16;
                a[mf][0] = As[(bm+gID  )*APAD + k + tig];
                a[mf][1] = As[(bm+gID+8)*APAD + k + tig];
                a[mf][2] = As[(bm+gID  )*APAD + k + tig + 4];
                a[mf][3] = As[(bm+gID+8)*APAD + k + tig + 4];
            }
            unsigned b[8][2];
            #pragma unroll
            for (int nf=0; nf<8; nf++){
                int bnn = wn*64 + nf*8;
                b[nf][0] = Bs[(k+tig  )*BPAD + bnn + gID];
                b[nf][1] = Bs[(k+tig+4)*BPAD + bnn + gID];
            }
            #pragma unroll
            for (int mf=0; mf<2; mf++)
                #pragma unroll
                for (int nf=0; nf<8; nf++)
                    mma_tf32(c[mf][nf], a[mf], b[nf]);
        }
        __syncthreads();
    }

    #pragma unroll
    for (int mf=0; mf<2; mf++){
        int row0 = by*128 + wm*32 + mf*16 + gID;
        #pragma unroll
        for (int nf=0; nf<8; nf++){
            int col = bx*128 + wn*64 + nf*8 + tig*2;
            #pragma unroll
            for (int half=0; half<2; half++){
                long row = row0 + half*8;
                float v0 = c[mf][nf][half*2+0];
                float v1 = c[mf][nf][half*2+1];
                if (bias){ v0 += bias[col]; v1 += bias[col+1]; }
                if (accFlag){
                    float2 o = *(float2*)(Cm + row*Nn + col);
                    v0 += o.x; v1 += o.y;
                }
                if (act == 1){ v0 = tanhf(v0); v1 = tanhf(v1); }
                else if (act == 2){ v0 = sigmoidf_(v0); v1 = sigmoidf_(v1); }
                *(float2*)(Cm + row*Nn + col) = make_float2(v0, v1);
            }
        }
    }
}

// ---------------- small gemm + activation (act 0=none,1=tanh,2=sigmoid) ----------------
__global__ void small_gemm(const float* __restrict__ A, const float* __restrict__ B,
                           const float* __restrict__ bias, float* __restrict__ Cm,
                           int M, int Nn, int K, int act)
{
    long idx = (long)blockIdx.x*blockDim.x + threadIdx.x;
    if (idx >= (long)M*Nn) return;
    int col = (int)(idx % Nn);
    long row = idx / Nn;
    float acc = bias ? bias[col] : 0.f;
    const float* a = A + row*K;
    #pragma unroll 8
    for (int k=0;k<K;k++) acc += a[k]*__ldg(&B[(long)k*Nn+col]);
    if (act==1) acc = tanhf(acc);
    else if (act==2) acc = sigmoidf_(acc);
    Cm[idx] = acc;
}

// ---------------- GAT ----------------
__global__ void gat_scores(const float* __restrict__ h, const float* __restrict__ asrc,
                           const float* __restrict__ adst, float* __restrict__ ss,
                           float* __restrict__ sd)
{
    int idx = blockIdx.x*blockDim.x + threadIdx.x;   // T*NV*HH
    if (idx >= T_*NV*HH) return;
    int hh = idx % HH;
    long node = idx / HH;
    const float* hp = h + node*DG + hh*DHD;
    float a = 0.f, b = 0.f;
    #pragma unroll
    for (int d=0; d<DHD; d++){
        float v = hp[d];
        a += v*asrc[hh*DHD+d];
        b += v*adst[hh*DHD+d];
    }
    ss[idx] = a; sd[idx] = b;
}

// per-edge, all 8 heads
__global__ void edge_score_max(const int* __restrict__ ei, const float* __restrict__ ew,
                               const float* __restrict__ ss, const float* __restrict__ sd,
                               float* __restrict__ esc, float* __restrict__ m)
{
    long idx = (long)blockIdx.x*blockDim.x + threadIdx.x;   // T*EE
    if (idx >= (long)T_*EE) return;
    int e = (int)(idx % EE);
    int t = (int)(idx / EE);
    int src = ei[(long)t*2*EE + e];
    int dst = ei[(long)t*2*EE + EE + e];
    float w = ew[(long)t*EE + e];
    float4 s0 = *(const float4*)(ss + ((long)t*NV+src)*HH);
    float4 s1 = *(const float4*)(ss + ((long)t*NV+src)*HH + 4);
    float4 d0 = *(const float4*)(sd + ((long)t*NV+dst)*HH);
    float4 d1 = *(const float4*)(sd + ((long)t*NV+dst)*HH + 4);
    float sc[8] = {s0.x+d0.x, s0.y+d0.y, s0.z+d0.z, s0.w+d0.w,
                   s1.x+d1.x, s1.y+d1.y, s1.z+d1.z, s1.w+d1.w};
    float* mp = m + ((long)t*NV+dst)*HH;
    #pragma unroll
    for (int hh=0; hh<8; hh++){
        float s = sc[hh];
        s = (s > 0.f) ? s : 0.2f*s;
        s *= w;
        sc[hh] = s;
        atomicMaxF(&mp[hh], s);
    }
    float4* ep = (float4*)(esc + idx*HH);
    ep[0] = make_float4(sc[0],sc[1],sc[2],sc[3]);
    ep[1] = make_float4(sc[4],sc[5],sc[6],sc[7]);
}

__global__ void edge_exp_sum(const int* __restrict__ ei, const float* __restrict__ m,
                             float* __restrict__ esc, float* __restrict__ dn)
{
    long idx = (long)blockIdx.x*blockDim.x + threadIdx.x;   // T*EE
    if (idx >= (long)T_*EE) return;
    int e = (int)(idx % EE);
    int t = (int)(idx / EE);
    int dst = ei[(long)t*2*EE + EE + e];
    float4 m0 = *(const float4*)(m + ((long)t*NV+dst)*HH);
    float4 m1 = *(const float4*)(m + ((long)t*NV+dst)*HH + 4);
    float4 e0 = *(const float4*)(esc + idx*HH);
    float4 e1 = *(const float4*)(esc + idx*HH + 4);
    float ex[8] = {expf(e0.x-m0.x), expf(e0.y-m0.y), expf(e0.z-m0.z), expf(e0.w-m0.w),
                   expf(e1.x-m1.x), expf(e1.y-m1.y), expf(e1.z-m1.z), expf(e1.w-m1.w)};
    float* dp = dn + ((long)t*NV+dst)*HH;
    #pragma unroll
    for (int hh=0; hh<8; hh++) atomicAdd(&dp[hh], ex[hh]);
    float4* ep = (float4*)(esc + idx*HH);
    ep[0] = make_float4(ex[0],ex[1],ex[2],ex[3]);
    ep[1] = make_float4(ex[4],ex[5],ex[6],ex[7]);
}

__global__ void edge_agg(const int* __restrict__ ei, const float* __restrict__ esc,
                         const float* __restrict__ dn, const float* __restrict__ h,
                         float* __restrict__ out)
{
    long gtid = (long)blockIdx.x*blockDim.x + threadIdx.x;
    long wid = gtid >> 5;
    int lane = (int)(gtid & 31);
    if (wid >= (long)T_*EE) return;
    int e = (int)(wid % EE);
    int t = (int)(wid / EE);
    int src = ei[(long)t*2*EE + e];
    int dst = ei[(long)t*2*EE + EE + e];
    int hh = lane >> 2;
    float ex  = esc[((long)t*EE+e)*HH + hh];
    float den = dn[((long)t*NV+dst)*HH + hh];
    float alpha = ex / (den + 1e-16f);
    float4 hv = *(const float4*)(h + ((long)t*NV+src)*DG + lane*4);
    float* op = out + ((long)t*NV+dst)*DG + lane*4;
    atomicAdd(op+0, alpha*hv.x);
    atomicAdd(op+1, alpha*hv.y);
    atomicAdd(op+2, alpha*hv.z);
    atomicAdd(op+3, alpha*hv.w);
}

__global__ void elu_k(const float* __restrict__ in, float* __restrict__ o, long n){
    long i = (long)blockIdx.x*blockDim.x + threadIdx.x;
    if (i >= n) return;
    float v = in[i];
    o[i] = (v > 0.f) ? v : expm1f(v);
}

// ---------------- fuse ----------------
__global__ void fuse_pool(const float* __restrict__ x, const int* __restrict__ com,
                          const float* __restrict__ w, float* __restrict__ num,
                          float* __restrict__ cd)
{
    long idx = (long)blockIdx.x*blockDim.x + threadIdx.x;   // T*NV*DG
    if (idx >= (long)T_*NV*DG) return;
    int d = (int)(idx % DG);
    long tn = idx / DG;
    int t = (int)(tn / NV);
    int c = com[tn];
    float wv = w[tn];
    atomicAdd(&num[((long)t*CC+c)*DG + d], wv * x[idx]);
    if (d == 0) atomicAdd(&cd[(long)t*CC + c], wv);
}

__global__ void fuse_finalize(const float* __restrict__ num, const float* __restrict__ cd,
                              float* __restrict__ meso, float* __restrict__ mac)
{
    int t = blockIdx.x;
    int d = threadIdx.x;   // 128
    float macn = 0.f, ws = 0.f;
    for (int c=0;c<CC;c++){
        float nv = num[((long)t*CC+c)*DG + d];
        float dv = cd[(long)t*CC + c];
        meso[((long)t*CC+c)*DG + d] = nv/(dv + 1e-16f);
        macn += nv; ws += dv;
    }
    mac[(long)t*DG + d] = macn/(ws + 1e-16f);
}

__global__ void fuse_mix(const float* __restrict__ x, const int* __restrict__ com,
                         const float* __restrict__ meso, const float* __restrict__ mac,
                         float* __restrict__ agg)
{
    long gtid = (long)blockIdx.x*blockDim.x + threadIdx.x;
    long wid = gtid >> 5;
    int lane = (int)(gtid & 31);
    if (wid >= (long)T_*NV) return;
    long tn = wid;
    int t = (int)(tn / NV);
    int c = com[tn];
    float4 mi = *(const float4*)(x + tn*DG + lane*4);
    float4 me = *(const float4*)(meso + ((long)t*CC+c)*DG + lane*4);
    float4 ma = *(const float4*)(mac + (long)t*DG + lane*4);
    float s0 = mi.x+mi.y+mi.z+mi.w;
    float s1 = me.x+me.y+me.z+me.w;
    float s2 = ma.x+ma.y+ma.z+ma.w;
    #pragma unroll
    for (int o=16;o>0;o>>=1){
        s0 += __shfl_xor_sync(0xffffffffu, s0, o);
        s1 += __shfl_xor_sync(0xffffffffu, s1, o);
        s2 += __shfl_xor_sync(0xffffffffu, s2, o);
    }
    s0 *= (1.f/DG); s1 *= (1.f/DG); s2 *= (1.f/DG);
    s0 = (s0>0.f)?s0:0.2f*s0;
    s1 = (s1>0.f)?s1:0.2f*s1;
    s2 = (s2>0.f)?s2:0.2f*s2;
    float mx = fmaxf(s0, fmaxf(s1, s2));
    float e0 = expf(s0-mx), e1 = expf(s1-mx), e2 = expf(s2-mx);
    float inv = 1.f/(e0+e1+e2);
    float a0 = e0*inv, a1 = e1*inv, a2 = e2*inv;
    float* ap = agg + tn*DAGG + lane*4;
    *(float4*)(ap)        = make_float4(a0*mi.x, a0*mi.y, a0*mi.z, a0*mi.w);
    *(float4*)(ap + DG)   = make_float4(a1*me.x, a1*me.y, a1*me.z, a1*me.w);
    *(float4*)(ap + 2*DG) = make_float4(a2*ma.x, a2*ma.y, a2*ma.z, a2*ma.w);
}

// ---------------- LSTM ----------------
__global__ void lstm_gate(const float* __restrict__ z, float* __restrict__ hs,
                          float* __restrict__ cs)
{
    long idx = (long)blockIdx.x*blockDim.x + threadIdx.x;
    if (idx >= (long)NV*DR) return;
    long n = idx / DR;
    int j = (int)(idx % DR);
    const float* zp = z + n*4*DR;
    float zi = zp[j], zf = zp[DR+j], zg = zp[2*DR+j], zo = zp[3*DR+j];
    float c = sigmoidf_(zf)*cs[idx] + sigmoidf_(zi)*tanhf(zg);
    cs[idx] = c;
    hs[idx] = sigmoidf_(zo)*tanhf(c);
}

// ---------------- decoder normalization ----------------
__global__ void colnorm_k(const float* __restrict__ emb, float* __restrict__ cni){
    int col = blockIdx.x;   // 64
    __shared__ float red[256];
    float s = 0.f;
    for (int n = threadIdx.x; n < NV; n += 256){
        float v = emb[(long)n*DD2 + col];
        s += v*v;
    }
    red[threadIdx.x] = s;
    __syncthreads();
    for (int o=128;o>0;o>>=1){
        if (threadIdx.x < o) red[threadIdx.x] += red[threadIdx.x+o];
        __syncthreads();
    }
    if (threadIdx.x == 0) cni[col] = 1.f / fmaxf(sqrtf(red[0]), 1e-12f);
}

__global__ void norm_sq(const float* __restrict__ emb, const float* __restrict__ cni,
                        float* __restrict__ embn, float* __restrict__ sq)
{
    long gtid = (long)blockIdx.x*blockDim.x + threadIdx.x;
    long row = gtid >> 5;
    int lane = (int)(gtid & 31);
    if (row >= NV) return;
    float a = emb[row*DD2 + lane]      * cni[lane];
    float b = emb[row*DD2 + 32 + lane] * cni[32 + lane];
    embn[row*DD2 + lane] = a;
    embn[row*DD2 + 32 + lane] = b;
    float s = a*a + b*b;
    #pragma unroll
    for (int o=16;o>0;o>>=1) s += __shfl_xor_sync(0xffffffffu, s, o);
    if (lane == 0) sq[row] = s;
}

// ---------------- adjacency ----------------
__global__ void __launch_bounds__(256) adj_k(const float* __restrict__ embn,
                                             const float* __restrict__ scal,
                                             const float* __restrict__ sq,
                                             float* __restrict__ out)
{
    extern __shared__ float sm[];
    const int LD = 68;
    float* eI = sm;
    float* eJ = eI + 64*LD;
    float* sI = eJ + 64*LD;
    float* sJ = sI + 64*LD;
    float* sqI = sJ + 64*LD;
    float* sqJ = sqI + 64;

    int bi = blockIdx.y, bj = blockIdx.x;
    int tid = threadIdx.x;

    for (int i = tid; i < 64*16; i += 256){
        int r  = i >> 4;
        int k4 = (i & 15) * 4;
        float4 v;
        v = *(const float4*)(embn + ((long)(bi*64+r))*DD2 + k4);
        eI[(k4+0)*LD+r]=v.x; eI[(k4+1)*LD+r]=v.y; eI[(k4+2)*LD+r]=v.z; eI[(k4+3)*LD+r]=v.w;
        v = *(const float4*)(embn + ((long)(bj*64+r))*DD2 + k4);
        eJ[(k4+0)*LD+r]=v.x; eJ[(k4+1)*LD+r]=v.y; eJ[(k4+2)*LD+r]=v.z; eJ[(k4+3)*LD+r]=v.w;
        v = *(const float4*)(scal + ((long)(bi*64+r))*DD2 + k4);
        sI[(k4+0)*LD+r]=v.x; sI[(k4+1)*LD+r]=v.y; sI[(k4+2)*LD+r]=v.z; sI[(k4+3)*LD+r]=v.w;
        v = *(const float4*)(scal + ((long)(bj*64+r))*DD2 + k4);
        sJ[(k4+0)*LD+r]=v.x; sJ[(k4+1)*LD+r]=v.y; sJ[(k4+2)*LD+r]=v.z; sJ[(k4+3)*LD+r]=v.w;
    }
    if (tid < 64){ sqI[tid] = sq[bi*64+tid]; sqJ[tid] = sq[bj*64+tid]; }
    __syncthreads();

    int ti = tid >> 4, tj = tid & 15;
    int i0 = ti*4, j0 = tj*4;
    float dac[4][4] = {};
    float sac[4][4] = {};
    #pragma unroll 4
    for (int k=0;k<64;k++){
        float4 va  = *(float4*)&eI[k*LD + i0];
        float4 vb  = *(float4*)&eJ[k*LD + j0];
        float4 vsa = *(float4*)&sI[k*LD + i0];
        float4 vsb = *(float4*)&sJ[k*LD + j0];
        float A_[4]  = {va.x,va.y,va.z,va.w};
        float B_[4]  = {vb.x,vb.y,vb.z,vb.w};
        float SA_[4] = {vsa.x,vsa.y,vsa.z,vsa.w};
        float SB_[4] = {vsb.x,vsb.y,vsb.z,vsb.w};
        #pragma unroll
        for (int r=0;r<4;r++)
            #pragma unroll
            for (int c=0;c<4;c++){
                dac[r][c] += A_[r]*B_[c];
                sac[r][c] += SA_[r]*SB_[c];
            }
    }

    #pragma unroll
    for (int r=0;r<4;r++){
        long row = (long)(bi*64 + i0 + r);
        float si = sqI[i0+r];
        float4 o;
        float d0 = si + sqJ[j0+0] - 2.f*dac[r][0];
        float d1 = si + sqJ[j0+1] - 2.f*dac[r][1];
        float d2 = si + sqJ[j0+2] - 2.f*dac[r][2];
        float d3 = si + sqJ[j0+3] - 2.f*dac[r][3];
        o.x = 1.f + tanhf(-d0*sac[r][0]);
        o.y = 1.f + tanhf(-d1*sac[r][1]);
        o.z = 1.f + tanhf(-d2*sac[r][2]);
        o.w = 1.f + tanhf(-d3*sac[r][3]);
        *(float4*)(out + row*NV + bj*64 + j0) = o;
    }
}

// ---------------- launch ----------------
static inline unsigned nb(long n, int b){ return (unsigned)((n + b - 1) / b); }

extern "C" void kernel_launch(void* const* d_in, const int* in_sizes, int n_in,
                              void* d_out, int out_size)
{
    (void)in_sizes; (void)n_in; (void)out_size;
    const int*   ei   = (const int*)  d_in[0];
    const float* ew   = (const float*)d_in[1];
    const float* feat = (const float*)d_in[2];
    const int*   com  = (const int*)  d_in[3];
    const float* nw   = (const float*)d_in[4];
    const float* gatW = (const float*)d_in[5];
    const float* asrc = (const float*)d_in[6];
    const float* adst = (const float*)d_in[7];
    const float* lWx  = (const float*)d_in[8];
    const float* lWh  = (const float*)d_in[9];
    const float* lb   = (const float*)d_in[10];
    const float* eW0  = (const float*)d_in[11];
    const float* eb0  = (const float*)d_in[12];
    const float* eW1  = (const float*)d_in[13];
    const float* eb1  = (const float*)d_in[14];
    const float* sW0  = (const float*)d_in[15];
    const float* sb0  = (const float*)d_in[16];
    const float* sW1  = (const float*)d_in[17];
    const float* sb1  = (const float*)d_in[18];
    float* out = (float*)d_out;

    float* buf = nullptr;
    cudaGetSymbolAddress((void**)&buf, g_buf);
    float* bH   = buf + OFF_H;
    float* bX   = buf + OFF_X;
    float* bSS  = buf + OFF_SS;
    float* bSD  = buf + OFF_SD;
    float* bE   = buf + OFF_E;
    float* bM   = buf + OFF_M;
    float* bDN  = buf + OFF_DN;
    float* bO   = buf + OFF_O;
    float* bNUM = buf + OFF_NUM;
    float* bCD  = buf + OFF_CD;
    float* bMES = buf + OFF_MES;
    float* bMAC = buf + OFF_MAC;
    float* bAGG = buf + OFF_AGG;
    float* bZX  = buf + OFF_ZX;
    float* bHS  = buf + OFF_HS;
    float* bCS  = buf + OFF_CS;
    float* bE1  = buf + OFF_E1;
    float* bEMB = buf + OFF_EMB;
    float* bEMBN= buf + OFF_EMBN;
    float* bS1  = buf + OFF_S1;
    float* bSC  = buf + OFF_SC;
    float* bSQ  = buf + OFF_SQ;
    float* bCNI = buf + OFF_CNI;

    // -------- GAT layers --------
    const float* xin = feat;
    for (int l = 0; l < 2; l++){
        gemm_tf32<<<dim3(DG/128, (T_*NV)/128), 256>>>(xin, gatW + (long)l*DG*DG, nullptr,
                                                      bH, T_*NV, DG, DG, 0, 0);
        gat_scores<<<nb((long)T_*NV*HH, 256), 256>>>(bH, asrc + l*HH*DHD, adst + l*HH*DHD,
                                                     bSS, bSD);
        fillk<<<nb((long)T_*NV*HH, 256), 256>>>(bM,  (long)T_*NV*HH, -INFINITY);
        fillk<<<nb((long)T_*NV*HH, 256), 256>>>(bDN, (long)T_*NV*HH, 0.f);
        fillk<<<nb((long)T_*NV*DG, 256), 256>>>(bO,  (long)T_*NV*DG, 0.f);
        edge_score_max<<<nb((long)T_*EE, 256), 256>>>(ei, ew, bSS, bSD, bE, bM);
        edge_exp_sum<<<nb((long)T_*EE, 256), 256>>>(ei, bM, bE, bDN);
        edge_agg<<<nb((long)T_*EE*32, 256), 256>>>(ei, bE, bDN, bH, bO);
        elu_k<<<nb((long)T_*NV*DG, 256), 256>>>(bO, bX, (long)T_*NV*DG);
        xin = bX;
    }

    // -------- hierarchical fuse --------
    fillk<<<nb((long)T_*CC*DG, 256), 256>>>(bNUM, (long)T_*CC*DG, 0.f);
    fillk<<<nb((long)T_*CC, 256), 256>>>(bCD, (long)T_*CC, 0.f);
    fuse_pool<<<nb((long)T_*NV*DG, 256), 256>>>(bX, com, nw, bNUM, bCD);
    fuse_finalize<<<T_, 128>>>(bNUM, bCD, bMES, bMAC);
    fuse_mix<<<nb((long)T_*NV*32, 256), 256>>>(bX, com, bMES, bMAC, bAGG);

    // -------- LSTM --------
    // Zx for ALL timesteps in one big tensor-core gemm: [T*NV, DAGG] @ [DAGG, 4DR] + b
    gemm_tf32<<<dim3((4*DR)/128, (T_*NV)/128), 256>>>(bAGG, lWx, lb, bZX,
                                                      T_*NV, 4*DR, DAGG, 0, 0);
    fillk<<<nb((long)NV*DR, 256), 256>>>(bHS, (long)NV*DR, 0.f);
    fillk<<<nb((long)NV*DR, 256), 256>>>(bCS, (long)NV*DR, 0.f);
    for (int t = 0; t < T_; t++){
        float* zt = bZX + (long)t*NV*4*DR;
        gemm_tf32<<<dim3((4*DR)/128, NV/128), 256>>>(bHS, lWh, nullptr, zt,
                                                     NV, 4*DR, DR, 1, 0);
        lstm_gate<<<nb((long)NV*DR, 256), 256>>>(zt, bHS, bCS);
    }

    // -------- decoders --------
    gemm_tf32<<<dim3(DD1/128, NV/128), 256>>>(bHS, eW0, eb0, bE1, NV, DD1, DR, 0, 1);
    small_gemm<<<nb((long)NV*DD2, 256), 256>>>(bE1, eW1, eb1, bEMB, NV, DD2, DD1, 1);
    gemm_tf32<<<dim3(DD1/128, NV/128), 256>>>(bHS, sW0, sb0, bS1, NV, DD1, DR, 0, 2);
    small_gemm<<<nb((long)NV*DD2, 256), 256>>>(bS1, sW1, sb1, bSC, NV, DD2, DD1, 2);

    colnorm_k<<<DD2, 256>>>(bEMB, bCNI);
    norm_sq<<<nb((long)NV*32, 256), 256>>>(bEMB, bCNI, bEMBN, bSQ);

    // -------- adjacency + emb output --------
    static const int adj_smem = (4*64*68 + 128) * (int)sizeof(float);
    cudaFuncSetAttribute(adj_k, cudaFuncAttributeMaxDynamicSharedMemorySize, adj_smem);
    adj_k<<<dim3(NV/64, NV/64), 256, adj_smem>>>(bEMBN, bSC, bSQ, out);
    copyk<<<nb((long)NV*DD2, 256), 256>>>(bEMB, out + (long)NV*NV, (long)NV*DD2);
}

// round 3
// speedup vs baseline: 1.7760x; 1.1982x over previous
#include <cuda_runtime.h>
#include <math.h>

#define T_   8
#define NV   8192
#define EE   131072
#define HH   8
#define CC   100
#define DG   128
#define DHD  16
#define DAGG 384
#define DR   256
#define DD1  128
#define DD2  64

// ---------------- scratch layout (floats) ----------------
constexpr long OFF_H    = 0;                                   // [T*NV*DG]
constexpr long OFF_X    = OFF_H    + (long)T_*NV*DG;           // [T*NV*DG]
constexpr long OFF_SS   = OFF_X    + (long)T_*NV*DG;           // [T*NV*HH]
constexpr long OFF_SD   = OFF_SS   + (long)T_*NV*HH;
constexpr long OFF_E    = OFF_SD   + (long)T_*NV*HH;           // [T*EE*HH]
constexpr long OFF_M    = OFF_E    + (long)T_*EE*HH;           // [T*NV*HH] (unused now)
constexpr long OFF_DN   = OFF_M    + (long)T_*NV*HH;           // [T*NV*HH]
constexpr long OFF_O    = OFF_DN   + (long)T_*NV*HH;           // [T*NV*DG]
constexpr long OFF_NUM  = OFF_O    + (long)T_*NV*DG;           // [T*CC*DG]
constexpr long OFF_CD   = OFF_NUM  + (long)T_*CC*DG;           // [T*CC]
constexpr long OFF_MES  = OFF_CD   + (long)T_*CC;              // [T*CC*DG]
constexpr long OFF_MAC  = OFF_MES  + (long)T_*CC*DG;           // [T*DG]
constexpr long OFF_AGG  = OFF_MAC  + (long)T_*DG;              // [T*NV*DAGG]
constexpr long OFF_ZX   = OFF_AGG  + (long)T_*NV*DAGG;         // [T*NV*4*DR]
constexpr long OFF_HS   = OFF_ZX   + (long)T_*NV*4*DR;         // [NV*DR]
constexpr long OFF_CS   = OFF_HS   + (long)NV*DR;              // [NV*DR]
constexpr long OFF_E1   = OFF_CS   + (long)NV*DR;              // [NV*DD1]
constexpr long OFF_EMB  = OFF_E1   + (long)NV*DD1;             // [NV*DD2]
constexpr long OFF_EMBN = OFF_EMB  + (long)NV*DD2;             // [NV*DD2]
constexpr long OFF_S1   = OFF_EMBN + (long)NV*DD2;             // [NV*DD1]
constexpr long OFF_SC   = OFF_S1   + (long)NV*DD1;             // [NV*DD2]
constexpr long OFF_SQ   = OFF_SC   + (long)NV*DD2;             // [NV]
constexpr long OFF_CNI  = OFF_SQ   + (long)NV;                 // [DD2]
constexpr long TOTAL    = OFF_CNI  + (long)DD2;

__device__ float g_buf[TOTAL];

// ---------------- helpers ----------------
__device__ __forceinline__ float sigmoidf_(float x){ return 1.f/(1.f+expf(-x)); }

__device__ __forceinline__ unsigned f2tf(float x){
    unsigned r; asm("cvt.rna.tf32.f32 %0, %1;" : "=r"(r) : "f"(x)); return r;
}

__device__ __forceinline__ void mma_tf32(float* c, const unsigned* a, const unsigned* b){
    asm volatile("mma.sync.aligned.m16n8k8.row.col.f32.tf32.tf32.f32 "
        "{%0,%1,%2,%3}, {%4,%5,%6,%7}, {%8,%9}, {%0,%1,%2,%3};"
        : "+f"(c[0]),"+f"(c[1]),"+f"(c[2]),"+f"(c[3])
        : "r"(a[0]),"r"(a[1]),"r"(a[2]),"r"(a[3]), "r"(b[0]),"r"(b[1]));
}

__global__ void fillk(float* p, long n, float v){
    long i = (long)blockIdx.x*blockDim.x + threadIdx.x;
    if (i < n) p[i] = v;
}

__global__ void copyk(const float* __restrict__ a, float* __restrict__ b, long n){
    long i = (long)blockIdx.x*blockDim.x + threadIdx.x;
    if (i < n) b[i] = a[i];
}

// ---------------- tf32 tensor-core GEMM ----------------
// C[M,N] = (acc?C:0) + A[MxK]@B[KxN] (+bias) (+act). M%128==0, N%128==0, K%32==0.
#define APAD 36
#define BPAD 136
__global__ void __launch_bounds__(256) gemm_tf32(
    const float* __restrict__ A, const float* __restrict__ B,
    const float* __restrict__ bias, float* __restrict__ Cm,
    int M, int Nn, int K, int accFlag, int act)
{
    __shared__ unsigned As[128*APAD];
    __shared__ unsigned Bs[32*BPAD];
    const int bx = blockIdx.x, by = blockIdx.y, tid = threadIdx.x;
    const int wid = tid >> 5, lane = tid & 31;
    const int wm = wid >> 1, wn = wid & 1;
    const int gID = lane >> 2, tig = lane & 3;

    float c[2][8][4];
    #pragma unroll
    for (int i=0;i<2;i++)
        #pragma unroll
        for (int j=0;j<8;j++)
            #pragma unroll
            for (int q=0;q<4;q++) c[i][j][q] = 0.f;

    const int am = tid >> 3;
    const int akq = (tid & 7) * 4;
    const int bk = tid >> 3;
    const int bn = (tid & 7) * 4;

    for (int k0 = 0; k0 < K; k0 += 32){
        #pragma unroll
        for (int r = 0; r < 4; r++){
            int m = am + r*32;
            float4 v = *(const float4*)(A + (long)(by*128 + m)*K + k0 + akq);
            unsigned* p = &As[m*APAD + akq];
            p[0]=f2tf(v.x); p[1]=f2tf(v.y); p[2]=f2tf(v.z); p[3]=f2tf(v.w);
        }
        #pragma unroll
        for (int q = 0; q < 4; q++){
            int n = bn + q*32;
            float4 v = *(const float4*)(B + (long)(k0 + bk)*Nn + bx*128 + n);
            unsigned* p = &Bs[bk*BPAD + n];
            p[0]=f2tf(v.x); p[1]=f2tf(v.y); p[2]=f2tf(v.z); p[3]=f2tf(v.w);
        }
        __syncthreads();

        #pragma unroll
        for (int ks = 0; ks < 4; ks++){
            const int k = ks*8;
            unsigned a[2][4];
            #pragma unroll
            for (int mf=0; mf<2; mf++){
                int bm = wm*32 + mf*16;
                a[mf][0] = As[(bm+gID  )*APAD + k + tig];
                a[mf][1] = As[(bm+gID+8)*APAD + k + tig];
                a[mf][2] = As[(bm+gID  )*APAD + k + tig + 4];
                a[mf][3] = As[(bm+gID+8)*APAD + k + tig + 4];
            }
            unsigned b[8][2];
            #pragma unroll
            for (int nf=0; nf<8; nf++){
                int bnn = wn*64 + nf*8;
                b[nf][0] = Bs[(k+tig  )*BPAD + bnn + gID];
                b[nf][1] = Bs[(k+tig+4)*BPAD + bnn + gID];
            }
            #pragma unroll
            for (int mf=0; mf<2; mf++)
                #pragma unroll
                for (int nf=0; nf<8; nf++)
                    mma_tf32(c[mf][nf], a[mf], b[nf]);
        }
        __syncthreads();
    }

    #pragma unroll
    for (int mf=0; mf<2; mf++){
        int row0 = by*128 + wm*32 + mf*16 + gID;
        #pragma unroll
        for (int nf=0; nf<8; nf++){
            int col = bx*128 + wn*64 + nf*8 + tig*2;
            #pragma unroll
            for (int half=0; half<2; half++){
                long row = row0 + half*8;
                float v0 = c[mf][nf][half*2+0];
                float v1 = c[mf][nf][half*2+1];
                if (bias){ v0 += bias[col]; v1 += bias[col+1]; }
                if (accFlag){
                    float2 o = *(float2*)(Cm + row*Nn + col);
                    v0 += o.x; v1 += o.y;
                }
                if (act == 1){ v0 = tanhf(v0); v1 = tanhf(v1); }
                else if (act == 2){ v0 = sigmoidf_(v0); v1 = sigmoidf_(v1); }
                *(float2*)(Cm + row*Nn + col) = make_float2(v0, v1);
            }
        }
    }
}

// ---------------- small gemm + activation ----------------
__global__ void small_gemm(const float* __restrict__ A, const float* __restrict__ B,
                           const float* __restrict__ bias, float* __restrict__ Cm,
                           int M, int Nn, int K, int act)
{
    long idx = (long)blockIdx.x*blockDim.x + threadIdx.x;
    if (idx >= (long)M*Nn) return;
    int col = (int)(idx % Nn);
    long row = idx / Nn;
    float acc = bias ? bias[col] : 0.f;
    const float* a = A + row*K;
    #pragma unroll 8
    for (int k=0;k<K;k++) acc += a[k]*__ldg(&B[(long)k*Nn+col]);
    if (act==1) acc = tanhf(acc);
    else if (act==2) acc = sigmoidf_(acc);
    Cm[idx] = acc;
}

// ---------------- GAT ----------------
__global__ void gat_scores(const float* __restrict__ h, const float* __restrict__ asrc,
                           const float* __restrict__ adst, float* __restrict__ ss,
                           float* __restrict__ sd)
{
    int idx = blockIdx.x*blockDim.x + threadIdx.x;   // T*NV*HH
    if (idx >= T_*NV*HH) return;
    int hh = idx % HH;
    long node = idx / HH;
    const float* hp = h + node*DG + hh*DHD;
    float a = 0.f, b = 0.f;
    #pragma unroll
    for (int d=0; d<DHD; d++){
        float v = hp[d];
        a += v*asrc[hh*DHD+d];
        b += v*adst[hh*DHD+d];
    }
    ss[idx] = a; sd[idx] = b;
}

// merged: scores -> leaky -> *ew -> exp -> store + atomic denominator
// (softmax shift dropped: logits bounded, shift-invariant)
__global__ void edge_softmax(const int* __restrict__ ei, const float* __restrict__ ew,
                             const float* __restrict__ ss, const float* __restrict__ sd,
                             float* __restrict__ esc, float* __restrict__ dn)
{
    long idx = (long)blockIdx.x*blockDim.x + threadIdx.x;   // T*EE
    if (idx >= (long)T_*EE) return;
    int e = (int)(idx % EE);
    int t = (int)(idx / EE);
    int src = ei[(long)t*2*EE + e];
    int dst = ei[(long)t*2*EE + EE + e];
    float w = ew[(long)t*EE + e];
    float4 s0 = *(const float4*)(ss + ((long)t*NV+src)*HH);
    float4 s1 = *(const float4*)(ss + ((long)t*NV+src)*HH + 4);
    float4 d0 = *(const float4*)(sd + ((long)t*NV+dst)*HH);
    float4 d1 = *(const float4*)(sd + ((long)t*NV+dst)*HH + 4);
    float sc[8] = {s0.x+d0.x, s0.y+d0.y, s0.z+d0.z, s0.w+d0.w,
                   s1.x+d1.x, s1.y+d1.y, s1.z+d1.z, s1.w+d1.w};
    float* dp = dn + ((long)t*NV+dst)*HH;
    #pragma unroll
    for (int hh=0; hh<8; hh++){
        float s = sc[hh];
        s = (s > 0.f) ? s : 0.2f*s;
        s *= w;
        float ex = expf(s);
        sc[hh] = ex;
        atomicAdd(&dp[hh], ex);
    }
    float4* ep = (float4*)(esc + idx*HH);
    ep[0] = make_float4(sc[0],sc[1],sc[2],sc[3]);
    ep[1] = make_float4(sc[4],sc[5],sc[6],sc[7]);
}

__global__ void edge_agg(const int* __restrict__ ei, const float* __restrict__ esc,
                         const float* __restrict__ dn, const float* __restrict__ h,
                         float* __restrict__ out)
{
    long gtid = (long)blockIdx.x*blockDim.x + threadIdx.x;
    long wid = gtid >> 5;
    int lane = (int)(gtid & 31);
    if (wid >= (long)T_*EE) return;
    int e = (int)(wid % EE);
    int t = (int)(wid / EE);
    int src = ei[(long)t*2*EE + e];
    int dst = ei[(long)t*2*EE + EE + e];
    int hh = lane >> 2;
    float ex  = esc[((long)t*EE+e)*HH + hh];
    float den = dn[((long)t*NV+dst)*HH + hh];
    float alpha = ex / (den + 1e-16f);
    float4 hv = *(const float4*)(h + ((long)t*NV+src)*DG + lane*4);
    float* op = out + ((long)t*NV+dst)*DG + lane*4;
    atomicAdd(op+0, alpha*hv.x);
    atomicAdd(op+1, alpha*hv.y);
    atomicAdd(op+2, alpha*hv.z);
    atomicAdd(op+3, alpha*hv.w);
}

__global__ void elu_k(const float* __restrict__ in, float* __restrict__ o, long n){
    long i = (long)blockIdx.x*blockDim.x + threadIdx.x;
    if (i >= n) return;
    float v = in[i];
    o[i] = (v > 0.f) ? v : expm1f(v);
}

// ---------------- fuse ----------------
__global__ void fuse_pool(const float* __restrict__ x, const int* __restrict__ com,
                          const float* __restrict__ w, float* __restrict__ num,
                          float* __restrict__ cd)
{
    long idx = (long)blockIdx.x*blockDim.x + threadIdx.x;   // T*NV*DG
    if (idx >= (long)T_*NV*DG) return;
    int d = (int)(idx % DG);
    long tn = idx / DG;
    int t = (int)(tn / NV);
    int c = com[tn];
    float wv = w[tn];
    atomicAdd(&num[((long)t*CC+c)*DG + d], wv * x[idx]);
    if (d == 0) atomicAdd(&cd[(long)t*CC + c], wv);
}

__global__ void fuse_finalize(const float* __restrict__ num, const float* __restrict__ cd,
                              float* __restrict__ meso, float* __restrict__ mac)
{
    int t = blockIdx.x;
    int d = threadIdx.x;   // 128
    float macn = 0.f, ws = 0.f;
    for (int c=0;c<CC;c++){
        float nv = num[((long)t*CC+c)*DG + d];
        float dv = cd[(long)t*CC + c];
        meso[((long)t*CC+c)*DG + d] = nv/(dv + 1e-16f);
        macn += nv; ws += dv;
    }
    mac[(long)t*DG + d] = macn/(ws + 1e-16f);
}

__global__ void fuse_mix(const float* __restrict__ x, const int* __restrict__ com,
                         const float* __restrict__ meso, const float* __restrict__ mac,
                         float* __restrict__ agg)
{
    long gtid = (long)blockIdx.x*blockDim.x + threadIdx.x;
    long wid = gtid >> 5;
    int lane = (int)(gtid & 31);
    if (wid >= (long)T_*NV) return;
    long tn = wid;
    int t = (int)(tn / NV);
    int c = com[tn];
    float4 mi = *(const float4*)(x + tn*DG + lane*4);
    float4 me = *(const float4*)(meso + ((long)t*CC+c)*DG + lane*4);
    float4 ma = *(const float4*)(mac + (long)t*DG + lane*4);
    float s0 = mi.x+mi.y+mi.z+mi.w;
    float s1 = me.x+me.y+me.z+me.w;
    float s2 = ma.x+ma.y+ma.z+ma.w;
    #pragma unroll
    for (int o=16;o>0;o>>=1){
        s0 += __shfl_xor_sync(0xffffffffu, s0, o);
        s1 += __shfl_xor_sync(0xffffffffu, s1, o);
        s2 += __shfl_xor_sync(0xffffffffu, s2, o);
    }
    s0 *= (1.f/DG); s1 *= (1.f/DG); s2 *= (1.f/DG);
    s0 = (s0>0.f)?s0:0.2f*s0;
    s1 = (s1>0.f)?s1:0.2f*s1;
    s2 = (s2>0.f)?s2:0.2f*s2;
    float mx = fmaxf(s0, fmaxf(s1, s2));
    float e0 = expf(s0-mx), e1 = expf(s1-mx), e2 = expf(s2-mx);
    float inv = 1.f/(e0+e1+e2);
    float a0 = e0*inv, a1 = e1*inv, a2 = e2*inv;
    float* ap = agg + tn*DAGG + lane*4;
    *(float4*)(ap)        = make_float4(a0*mi.x, a0*mi.y, a0*mi.z, a0*mi.w);
    *(float4*)(ap + DG)   = make_float4(a1*me.x, a1*me.y, a1*me.z, a1*me.w);
    *(float4*)(ap + 2*DG) = make_float4(a2*ma.x, a2*ma.y, a2*ma.z, a2*ma.w);
}

// ---------------- LSTM ----------------
__global__ void lstm_gate(const float* __restrict__ z, float* __restrict__ hs,
                          float* __restrict__ cs)
{
    long idx = (long)blockIdx.x*blockDim.x + threadIdx.x;
    if (idx >= (long)NV*DR) return;
    long n = idx / DR;
    int j = (int)(idx % DR);
    const float* zp = z + n*4*DR;
    float zi = zp[j], zf = zp[DR+j], zg = zp[2*DR+j], zo = zp[3*DR+j];
    float c = sigmoidf_(zf)*cs[idx] + sigmoidf_(zi)*tanhf(zg);
    cs[idx] = c;
    hs[idx] = sigmoidf_(zo)*tanhf(c);
}

// ---------------- decoder normalization ----------------
__global__ void colnorm_k(const float* __restrict__ emb, float* __restrict__ cni){
    int col = blockIdx.x;   // 64
    __shared__ float red[256];
    float s = 0.f;
    for (int n = threadIdx.x; n < NV; n += 256){
        float v = emb[(long)n*DD2 + col];
        s += v*v;
    }
    red[threadIdx.x] = s;
    __syncthreads();
    for (int o=128;o>0;o>>=1){
        if (threadIdx.x < o) red[threadIdx.x] += red[threadIdx.x+o];
        __syncthreads();
    }
    if (threadIdx.x == 0) cni[col] = 1.f / fmaxf(sqrtf(red[0]), 1e-12f);
}

__global__ void norm_sq(const float* __restrict__ emb, const float* __restrict__ cni,
                        float* __restrict__ embn, float* __restrict__ sq)
{
    long gtid = (long)blockIdx.x*blockDim.x + threadIdx.x;
    long row = gtid >> 5;
    int lane = (int)(gtid & 31);
    if (row >= NV) return;
    float a = emb[row*DD2 + lane]      * cni[lane];
    float b = emb[row*DD2 + 32 + lane] * cni[32 + lane];
    embn[row*DD2 + lane] = a;
    embn[row*DD2 + 32 + lane] = b;
    float s = a*a + b*b;
    #pragma unroll
    for (int o=16;o>0;o>>=1) s += __shfl_xor_sync(0xffffffffu, s, o);
    if (lane == 0) sq[row] = s;
}

// ---------------- adjacency: dual tf32 gram + tanh epilogue ----------------
#define ALD 68
#define BLD 136
__global__ void __launch_bounds__(256) adj_tc(
    const float* __restrict__ embn, const float* __restrict__ scal,
    const float* __restrict__ sq, float* __restrict__ out)
{
    extern __shared__ unsigned smu[];
    unsigned* AE = smu;                    // [128][ALD]
    unsigned* AS = AE + 128*ALD;
    unsigned* BE = AS + 128*ALD;           // [64][BLD] (k-major)
    unsigned* BS = BE + 64*BLD;
    float* sqI = (float*)(BS + 64*BLD);    // [128]
    float* sqJ = sqI + 128;

    const int bi = blockIdx.y, bj = blockIdx.x, tid = threadIdx.x;
    const int wid = tid >> 5, lane = tid & 31;
    const int wm = wid >> 1, wn = wid & 1;
    const int gID = lane >> 2, tig = lane & 3;

    // A tiles: coalesced row-major loads
    for (int i = tid; i < 128*16; i += 256){
        int r = i >> 4, c4 = (i & 15) * 4;
        float4 v = *(const float4*)(embn + ((long)(bi*128+r))*DD2 + c4);
        unsigned* p = &AE[r*ALD + c4];
        p[0]=f2tf(v.x); p[1]=f2tf(v.y); p[2]=f2tf(v.z); p[3]=f2tf(v.w);
        v = *(const float4*)(scal + ((long)(bi*128+r))*DD2 + c4);
        p = &AS[r*ALD + c4];
        p[0]=f2tf(v.x); p[1]=f2tf(v.y); p[2]=f2tf(v.z); p[3]=f2tf(v.w);
    }
    // B tiles: transpose-gather; lane->n keeps smem writes conflict-free
    for (int i = tid; i < 128*16; i += 256){
        int n = i & 127, c4 = (i >> 7) * 4;
        float4 v = *(const float4*)(embn + ((long)(bj*128+n))*DD2 + c4);
        BE[(c4+0)*BLD+n]=f2tf(v.x); BE[(c4+1)*BLD+n]=f2tf(v.y);
        BE[(c4+2)*BLD+n]=f2tf(v.z); BE[(c4+3)*BLD+n]=f2tf(v.w);
        v = *(const float4*)(scal + ((long)(bj*128+n))*DD2 + c4);
        BS[(c4+0)*BLD+n]=f2tf(v.x); BS[(c4+1)*BLD+n]=f2tf(v.y);
        BS[(c4+2)*BLD+n]=f2tf(v.z); BS[(c4+3)*BLD+n]=f2tf(v.w);
    }
    if (tid < 128){ sqI[tid] = sq[bi*128+tid]; sqJ[tid] = sq[bj*128+tid]; }
    __syncthreads();

    float cd[2][8][4], cs[2][8][4];
    #pragma unroll
    for (int i=0;i<2;i++)
        #pragma unroll
        for (int j=0;j<8;j++)
            #pragma unroll
            for (int q=0;q<4;q++){ cd[i][j][q]=0.f; cs[i][j][q]=0.f; }

    #pragma unroll
    for (int ks = 0; ks < 8; ks++){
        const int k = ks*8;
        unsigned aE[2][4], aS[2][4];
        #pragma unroll
        for (int mf=0; mf<2; mf++){
            int bm = wm*32 + mf*16;
            aE[mf][0] = AE[(bm+gID  )*ALD + k + tig];
            aE[mf][1] = AE[(bm+gID+8)*ALD + k + tig];
            aE[mf][2] = AE[(bm+gID  )*ALD + k + tig + 4];
            aE[mf][3] = AE[(bm+gID+8)*ALD + k + tig + 4];
            aS[mf][0] = AS[(bm+gID  )*ALD + k + tig];
            aS[mf][1] = AS[(bm+gID+8)*ALD + k + tig];
            aS[mf][2] = AS[(bm+gID  )*ALD + k + tig + 4];
            aS[mf][3] = AS[(bm+gID+8)*ALD + k + tig + 4];
        }
        unsigned bE[8][2], bS[8][2];
        #pragma unroll
        for (int nf=0; nf<8; nf++){
            int bnn = wn*64 + nf*8;
            bE[nf][0] = BE[(k+tig  )*BLD + bnn + gID];
            bE[nf][1] = BE[(k+tig+4)*BLD + bnn + gID];
            bS[nf][0] = BS[(k+tig  )*BLD + bnn + gID];
            bS[nf][1] = BS[(k+tig+4)*BLD + bnn + gID];
        }
        #pragma unroll
        for (int mf=0; mf<2; mf++)
            #pragma unroll
            for (int nf=0; nf<8; nf++){
                mma_tf32(cd[mf][nf], aE[mf], bE[nf]);
                mma_tf32(cs[mf][nf], aS[mf], bS[nf]);
            }
    }

    #pragma unroll
    for (int mf=0; mf<2; mf++){
        int rl0 = wm*32 + mf*16 + gID;
        #pragma unroll
        for (int nf=0; nf<8; nf++){
            int cl = wn*64 + nf*8 + tig*2;
            #pragma unroll
            for (int half=0; half<2; half++){
                int rl = rl0 + half*8;
                float sqi = sqI[rl];
                float d0 = sqi + sqJ[cl]   - 2.f*cd[mf][nf][half*2+0];
                float d1 = sqi + sqJ[cl+1] - 2.f*cd[mf][nf][half*2+1];
                float v0 = 1.f + tanhf(-d0*cs[mf][nf][half*2+0]);
                float v1 = 1.f + tanhf(-d1*cs[mf][nf][half*2+1]);
                *(float2*)(out + ((long)(bi*128+rl))*NV + bj*128 + cl) = make_float2(v0, v1);
            }
        }
    }
}

// ---------------- launch ----------------
static inline unsigned nb(long n, int b){ return (unsigned)((n + b - 1) / b); }

extern "C" void kernel_launch(void* const* d_in, const int* in_sizes, int n_in,
                              void* d_out, int out_size)
{
    (void)in_sizes; (void)n_in; (void)out_size;
    const int*   ei   = (const int*)  d_in[0];
    const float* ew   = (const float*)d_in[1];
    const float* feat = (const float*)d_in[2];
    const int*   com  = (const int*)  d_in[3];
    const float* nw   = (const float*)d_in[4];
    const float* gatW = (const float*)d_in[5];
    const float* asrc = (const float*)d_in[6];
    const float* adst = (const float*)d_in[7];
    const float* lWx  = (const float*)d_in[8];
    const float* lWh  = (const float*)d_in[9];
    const float* lb   = (const float*)d_in[10];
    const float* eW0  = (const float*)d_in[11];
    const float* eb0  = (const float*)d_in[12];
    const float* eW1  = (const float*)d_in[13];
    const float* eb1  = (const float*)d_in[14];
    const float* sW0  = (const float*)d_in[15];
    const float* sb0  = (const float*)d_in[16];
    const float* sW1  = (const float*)d_in[17];
    const float* sb1  = (const float*)d_in[18];
    float* out = (float*)d_out;

    float* buf = nullptr;
    cudaGetSymbolAddress((void**)&buf, g_buf);
    float* bH   = buf + OFF_H;
    float* bX   = buf + OFF_X;
    float* bSS  = buf + OFF_SS;
    float* bSD  = buf + OFF_SD;
    float* bE   = buf + OFF_E;
    float* bDN  = buf + OFF_DN;
    float* bO   = buf + OFF_O;
    float* bNUM = buf + OFF_NUM;
    float* bCD  = buf + OFF_CD;
    float* bMES = buf + OFF_MES;
    float* bMAC = buf + OFF_MAC;
    float* bAGG = buf + OFF_AGG;
    float* bZX  = buf + OFF_ZX;
    float* bHS  = buf + OFF_HS;
    float* bCS  = buf + OFF_CS;
    float* bE1  = buf + OFF_E1;
    float* bEMB = buf + OFF_EMB;
    float* bEMBN= buf + OFF_EMBN;
    float* bS1  = buf + OFF_S1;
    float* bSC  = buf + OFF_SC;
    float* bSQ  = buf + OFF_SQ;
    float* bCNI = buf + OFF_CNI;

    // -------- GAT layers --------
    const float* xin = feat;
    for (int l = 0; l < 2; l++){
        gemm_tf32<<<dim3(DG/128, (T_*NV)/128), 256>>>(xin, gatW + (long)l*DG*DG, nullptr,
                                                      bH, T_*NV, DG, DG, 0, 0);
        gat_scores<<<nb((long)T_*NV*HH, 256), 256>>>(bH, asrc + l*HH*DHD, adst + l*HH*DHD,
                                                     bSS, bSD);
        // bDN and bO are adjacent: single zero fill
        fillk<<<nb((long)T_*NV*(HH+DG), 256), 256>>>(bDN, (long)T_*NV*(HH+DG), 0.f);
        edge_softmax<<<nb((long)T_*EE, 256), 256>>>(ei, ew, bSS, bSD, bE, bDN);
        edge_agg<<<nb((long)T_*EE*32, 256), 256>>>(ei, bE, bDN, bH, bO);
        elu_k<<<nb((long)T_*NV*DG, 256), 256>>>(bO, bX, (long)T_*NV*DG);
        xin = bX;
    }

    // -------- hierarchical fuse --------
    fillk<<<nb((long)T_*CC*(DG+1), 256), 256>>>(bNUM, (long)T_*CC*(DG+1), 0.f);
    fuse_pool<<<nb((long)T_*NV*DG, 256), 256>>>(bX, com, nw, bNUM, bCD);
    fuse_finalize<<<T_, 128>>>(bNUM, bCD, bMES, bMAC);
    fuse_mix<<<nb((long)T_*NV*32, 256), 256>>>(bX, com, bMES, bMAC, bAGG);

    // -------- LSTM --------
    gemm_tf32<<<dim3((4*DR)/128, (T_*NV)/128), 256>>>(bAGG, lWx, lb, bZX,
                                                      T_*NV, 4*DR, DAGG, 0, 0);
    fillk<<<nb((long)2*NV*DR, 256), 256>>>(bHS, (long)2*NV*DR, 0.f);
    for (int t = 0; t < T_; t++){
        float* zt = bZX + (long)t*NV*4*DR;
        gemm_tf32<<<dim3((4*DR)/128, NV/128), 256>>>(bHS, lWh, nullptr, zt,
                                                     NV, 4*DR, DR, 1, 0);
        lstm_gate<<<nb((long)NV*DR, 256), 256>>>(zt, bHS, bCS);
    }

    // -------- decoders --------
    gemm_tf32<<<dim3(DD1/128, NV/128), 256>>>(bHS, eW0, eb0, bE1, NV, DD1, DR, 0, 1);
    small_gemm<<<nb((long)NV*DD2, 256), 256>>>(bE1, eW1, eb1, bEMB, NV, DD2, DD1, 1);
    gemm_tf32<<<dim3(DD1/128, NV/128), 256>>>(bHS, sW0, sb0, bS1, NV, DD1, DR, 0, 2);
    small_gemm<<<nb((long)NV*DD2, 256), 256>>>(bS1, sW1, sb1, bSC, NV, DD2, DD1, 2);

    colnorm_k<<<DD2, 256>>>(bEMB, bCNI);
    norm_sq<<<nb((long)NV*32, 256), 256>>>(bEMB, bCNI, bEMBN, bSQ);

    // -------- adjacency + emb output --------
    static const int adj_smem = (2*128*ALD + 2*64*BLD + 256) * (int)sizeof(unsigned);
    cudaFuncSetAttribute(adj_tc, cudaFuncAttributeMaxDynamicSharedMemorySize, adj_smem);
    adj_tc<<<dim3(NV/128, NV/128), 256, adj_smem>>>(bEMBN, bSC, bSQ, out);
    copyk<<<nb((long)NV*DD2, 256), 256>>>(bEMB, out + (long)NV*NV, (long)NV*DD2);
}

// round 4
// speedup vs baseline: 2.1274x; 1.1979x over previous
#include <cuda_runtime.h>
#include <math.h>

#define T_   8
#define NV   8192
#define EE   131072
#define HH   8
#define CC   100
#define DG   128
#define DHD  16
#define DAGG 384
#define DR   256
#define DD1  128
#define DD2  64

// ---------------- scratch layout (floats) ----------------
constexpr long OFF_H    = 0;                                   // [T*NV*DG]
constexpr long OFF_X    = OFF_H    + (long)T_*NV*DG;           // [T*NV*DG]
constexpr long OFF_SS   = OFF_X    + (long)T_*NV*DG;           // [T*NV*HH]
constexpr long OFF_SD   = OFF_SS   + (long)T_*NV*HH;
constexpr long OFF_E    = OFF_SD   + (long)T_*NV*HH;           // [T*EE*HH]
constexpr long OFF_DN   = OFF_E    + (long)T_*EE*HH;           // [T*NV*HH]
constexpr long OFF_O    = OFF_DN   + (long)T_*NV*HH;           // [T*NV*DG]
constexpr long OFF_NUM  = OFF_O    + (long)T_*NV*DG;           // [T*CC*DG]
constexpr long OFF_CD   = OFF_NUM  + (long)T_*CC*DG;           // [T*CC]
constexpr long OFF_MES  = OFF_CD   + (long)T_*CC;              // [T*CC*DG]
constexpr long OFF_MAC  = OFF_MES  + (long)T_*CC*DG;           // [T*DG]
constexpr long OFF_AGG  = OFF_MAC  + (long)T_*DG;              // [T*NV*DAGG]
constexpr long OFF_ZX   = OFF_AGG  + (long)T_*NV*DAGG;         // [T*NV*4*DR]
constexpr long OFF_HS   = OFF_ZX   + (long)T_*NV*4*DR;         // [NV*DR]
constexpr long OFF_CS   = OFF_HS   + (long)NV*DR;              // [NV*DR]
constexpr long OFF_E1   = OFF_CS   + (long)NV*DR;              // [NV*DD1]
constexpr long OFF_EMB  = OFF_E1   + (long)NV*DD1;             // [NV*DD2]
constexpr long OFF_EMBN = OFF_EMB  + (long)NV*DD2;             // [NV*DD2]
constexpr long OFF_S1   = OFF_EMBN + (long)NV*DD2;             // [NV*DD1]
constexpr long OFF_SC   = OFF_S1   + (long)NV*DD1;             // [NV*DD2]
constexpr long OFF_SQ   = OFF_SC   + (long)NV*DD2;             // [NV]
constexpr long OFF_CNI  = OFF_SQ   + (long)NV;                 // [DD2]
constexpr long TOTAL    = OFF_CNI  + (long)DD2;

__device__ float g_buf[TOTAL];

// ---------------- helpers ----------------
// fast sigmoid: __expf rel err ~1e-7; overflow -> exp=inf -> 1/inf=0 (correct limit)
__device__ __forceinline__ float fsig(float x){ return 1.f/(1.f+__expf(-x)); }
// fast tanh, overflow-guarded: t=e^{-2|x|} in (0,1], tanh=sign(x)*(1-t)/(1+t)
__device__ __forceinline__ float ftanh(float x){
    float t = __expf(-2.f*fabsf(x));
    float r = __fdividef(1.f - t, 1.f + t);
    return copysignf(r, x);
}

__device__ __forceinline__ unsigned f2tf(float x){
    unsigned r; asm("cvt.rna.tf32.f32 %0, %1;" : "=r"(r) : "f"(x)); return r;
}

__device__ __forceinline__ void mma_tf32(float* c, const unsigned* a, const unsigned* b){
    asm volatile("mma.sync.aligned.m16n8k8.row.col.f32.tf32.tf32.f32 "
        "{%0,%1,%2,%3}, {%4,%5,%6,%7}, {%8,%9}, {%0,%1,%2,%3};"
        : "+f"(c[0]),"+f"(c[1]),"+f"(c[2]),"+f"(c[3])
        : "r"(a[0]),"r"(a[1]),"r"(a[2]),"r"(a[3]), "r"(b[0]),"r"(b[1]));
}

__global__ void fillk(float* p, long n, float v){
    long i = (long)blockIdx.x*blockDim.x + threadIdx.x;
    if (i < n) p[i] = v;
}

__global__ void copyk(const float* __restrict__ a, float* __restrict__ b, long n){
    long i = (long)blockIdx.x*blockDim.x + threadIdx.x;
    if (i < n) b[i] = a[i];
}

// ---------------- tf32 tensor-core GEMM ----------------
// C[M,N] = (acc?C:0) + A[MxK]@B[KxN] (+bias) (+act). M%128==0, N%128==0, K%32==0.
#define APAD 36
#define BPAD 136
__global__ void __launch_bounds__(256) gemm_tf32(
    const float* __restrict__ A, const float* __restrict__ B,
    const float* __restrict__ bias, float* __restrict__ Cm,
    int M, int Nn, int K, int accFlag, int act)
{
    __shared__ unsigned As[128*APAD];
    __shared__ unsigned Bs[32*BPAD];
    const int bx = blockIdx.x, by = blockIdx.y, tid = threadIdx.x;
    const int wid = tid >> 5, lane = tid & 31;
    const int wm = wid >> 1, wn = wid & 1;
    const int gID = lane >> 2, tig = lane & 3;

    float c[2][8][4];
    #pragma unroll
    for (int i=0;i<2;i++)
        #pragma unroll
        for (int j=0;j<8;j++)
            #pragma unroll
            for (int q=0;q<4;q++) c[i][j][q] = 0.f;

    const int am = tid >> 3;
    const int akq = (tid & 7) * 4;
    const int bk = tid >> 3;
    const int bn = (tid & 7) * 4;

    for (int k0 = 0; k0 < K; k0 += 32){
        #pragma unroll
        for (int r = 0; r < 4; r++){
            int m = am + r*32;
            float4 v = *(const float4*)(A + (long)(by*128 + m)*K + k0 + akq);
            unsigned* p = &As[m*APAD + akq];
            p[0]=f2tf(v.x); p[1]=f2tf(v.y); p[2]=f2tf(v.z); p[3]=f2tf(v.w);
        }
        #pragma unroll
        for (int q = 0; q < 4; q++){
            int n = bn + q*32;
            float4 v = *(const float4*)(B + (long)(k0 + bk)*Nn + bx*128 + n);
            unsigned* p = &Bs[bk*BPAD + n];
            p[0]=f2tf(v.x); p[1]=f2tf(v.y); p[2]=f2tf(v.z); p[3]=f2tf(v.w);
        }
        __syncthreads();

        #pragma unroll
        for (int ks = 0; ks < 4; ks++){
            const int k = ks*8;
            unsigned a[2][4];
            #pragma unroll
            for (int mf=0; mf<2; mf++){
                int bm = wm*32 + mf*16;
                a[mf][0] = As[(bm+gID  )*APAD + k + tig];
                a[mf][1] = As[(bm+gID+8)*APAD + k + tig];
                a[mf][2] = As[(bm+gID  )*APAD + k + tig + 4];
                a[mf][3] = As[(bm+gID+8)*APAD + k + tig + 4];
            }
            unsigned b[8][2];
            #pragma unroll
            for (int nf=0; nf<8; nf++){
                int bnn = wn*64 + nf*8;
                b[nf][0] = Bs[(k+tig  )*BPAD + bnn + gID];
                b[nf][1] = Bs[(k+tig+4)*BPAD + bnn + gID];
            }
            #pragma unroll
            for (int mf=0; mf<2; mf++)
                #pragma unroll
                for (int nf=0; nf<8; nf++)
                    mma_tf32(c[mf][nf], a[mf], b[nf]);
        }
        __syncthreads();
    }

    #pragma unroll
    for (int mf=0; mf<2; mf++){
        int row0 = by*128 + wm*32 + mf*16 + gID;
        #pragma unroll
        for (int nf=0; nf<8; nf++){
            int col = bx*128 + wn*64 + nf*8 + tig*2;
            #pragma unroll
            for (int half=0; half<2; half++){
                long row = row0 + half*8;
                float v0 = c[mf][nf][half*2+0];
                float v1 = c[mf][nf][half*2+1];
                if (bias){ v0 += bias[col]; v1 += bias[col+1]; }
                if (accFlag){
                    float2 o = *(float2*)(Cm + row*Nn + col);
                    v0 += o.x; v1 += o.y;
                }
                if (act == 1){ v0 = ftanh(v0); v1 = ftanh(v1); }
                else if (act == 2){ v0 = fsig(v0); v1 = fsig(v1); }
                *(float2*)(Cm + row*Nn + col) = make_float2(v0, v1);
            }
        }
    }
}

// ---------------- small gemm + activation ----------------
__global__ void small_gemm(const float* __restrict__ A, const float* __restrict__ B,
                           const float* __restrict__ bias, float* __restrict__ Cm,
                           int M, int Nn, int K, int act)
{
    long idx = (long)blockIdx.x*blockDim.x + threadIdx.x;
    if (idx >= (long)M*Nn) return;
    int col = (int)(idx % Nn);
    long row = idx / Nn;
    float acc = bias ? bias[col] : 0.f;
    const float* a = A + row*K;
    #pragma unroll 8
    for (int k=0;k<K;k++) acc += a[k]*__ldg(&B[(long)k*Nn+col]);
    if (act==1) acc = ftanh(acc);
    else if (act==2) acc = fsig(acc);
    Cm[idx] = acc;
}

// ---------------- GAT ----------------
__global__ void gat_scores(const float* __restrict__ h, const float* __restrict__ asrc,
                           const float* __restrict__ adst, float* __restrict__ ss,
                           float* __restrict__ sd)
{
    int idx = blockIdx.x*blockDim.x + threadIdx.x;   // T*NV*HH
    if (idx >= T_*NV*HH) return;
    int hh = idx % HH;
    long node = idx / HH;
    const float* hp = h + node*DG + hh*DHD;
    float a = 0.f, b = 0.f;
    #pragma unroll
    for (int d=0; d<DHD; d++){
        float v = hp[d];
        a += v*asrc[hh*DHD+d];
        b += v*adst[hh*DHD+d];
    }
    ss[idx] = a; sd[idx] = b;
}

// merged: scores -> leaky -> *ew -> exp -> store + vector-atomic denominator
__global__ void edge_softmax(const int* __restrict__ ei, const float* __restrict__ ew,
                             const float* __restrict__ ss, const float* __restrict__ sd,
                             float* __restrict__ esc, float* __restrict__ dn)
{
    long idx = (long)blockIdx.x*blockDim.x + threadIdx.x;   // T*EE
    if (idx >= (long)T_*EE) return;
    int e = (int)(idx % EE);
    int t = (int)(idx / EE);
    int src = ei[(long)t*2*EE + e];
    int dst = ei[(long)t*2*EE + EE + e];
    float w = ew[(long)t*EE + e];
    float4 s0 = *(const float4*)(ss + ((long)t*NV+src)*HH);
    float4 s1 = *(const float4*)(ss + ((long)t*NV+src)*HH + 4);
    float4 d0 = *(const float4*)(sd + ((long)t*NV+dst)*HH);
    float4 d1 = *(const float4*)(sd + ((long)t*NV+dst)*HH + 4);
    float sc[8] = {s0.x+d0.x, s0.y+d0.y, s0.z+d0.z, s0.w+d0.w,
                   s1.x+d1.x, s1.y+d1.y, s1.z+d1.z, s1.w+d1.w};
    #pragma unroll
    for (int hh=0; hh<8; hh++){
        float s = sc[hh];
        s = (s > 0.f) ? s : 0.2f*s;
        sc[hh] = __expf(s * w);
    }
    float4* dp = (float4*)(dn + ((long)t*NV+dst)*HH);
    atomicAdd(dp,   make_float4(sc[0],sc[1],sc[2],sc[3]));
    atomicAdd(dp+1, make_float4(sc[4],sc[5],sc[6],sc[7]));
    float4* ep = (float4*)(esc + idx*HH);
    ep[0] = make_float4(sc[0],sc[1],sc[2],sc[3]);
    ep[1] = make_float4(sc[4],sc[5],sc[6],sc[7]);
}

__global__ void edge_agg(const int* __restrict__ ei, const float* __restrict__ esc,
                         const float* __restrict__ dn, const float* __restrict__ h,
                         float* __restrict__ out)
{
    long gtid = (long)blockIdx.x*blockDim.x + threadIdx.x;
    long wid = gtid >> 5;
    int lane = (int)(gtid & 31);
    if (wid >= (long)T_*EE) return;
    int e = (int)(wid % EE);
    int t = (int)(wid / EE);
    int src = ei[(long)t*2*EE + e];
    int dst = ei[(long)t*2*EE + EE + e];
    int hh = lane >> 2;
    float ex  = esc[((long)t*EE+e)*HH + hh];
    float den = dn[((long)t*NV+dst)*HH + hh];
    float alpha = __fdividef(ex, den + 1e-16f);
    float4 hv = *(const float4*)(h + ((long)t*NV+src)*DG + lane*4);
    float4* op = (float4*)(out + ((long)t*NV+dst)*DG + lane*4);
    atomicAdd(op, make_float4(alpha*hv.x, alpha*hv.y, alpha*hv.z, alpha*hv.w));
}

__global__ void elu_k(const float* __restrict__ in, float* __restrict__ o, long n){
    long i = (long)blockIdx.x*blockDim.x + threadIdx.x;
    if (i >= n) return;
    float v = in[i];
    o[i] = (v > 0.f) ? v : expm1f(v);
}

// ---------------- fuse ----------------
// float4-grain pooling: 4x fewer atomics
__global__ void fuse_pool(const float* __restrict__ x, const int* __restrict__ com,
                          const float* __restrict__ w, float* __restrict__ num,
                          float* __restrict__ cd)
{
    long idx = (long)blockIdx.x*blockDim.x + threadIdx.x;   // T*NV*32
    if (idx >= (long)T_*NV*32) return;
    int d4 = (int)(idx & 31);
    long tn = idx >> 5;
    int t = (int)(tn / NV);
    int c = com[tn];
    float wv = w[tn];
    float4 v = *(const float4*)(x + tn*DG + d4*4);
    float4* np = (float4*)(num + ((long)t*CC+c)*DG + d4*4);
    atomicAdd(np, make_float4(wv*v.x, wv*v.y, wv*v.z, wv*v.w));
    if (d4 == 0) atomicAdd(&cd[(long)t*CC + c], wv);
}

__global__ void fuse_finalize(const float* __restrict__ num, const float* __restrict__ cd,
                              float* __restrict__ meso, float* __restrict__ mac)
{
    int t = blockIdx.x;
    int d = threadIdx.x;   // 128
    float macn = 0.f, ws = 0.f;
    for (int c=0;c<CC;c++){
        float nv = num[((long)t*CC+c)*DG + d];
        float dv = cd[(long)t*CC + c];
        meso[((long)t*CC+c)*DG + d] = nv/(dv + 1e-16f);
        macn += nv; ws += dv;
    }
    mac[(long)t*DG + d] = macn/(ws + 1e-16f);
}

__global__ void fuse_mix(const float* __restrict__ x, const int* __restrict__ com,
                         const float* __restrict__ meso, const float* __restrict__ mac,
                         float* __restrict__ agg)
{
    long gtid = (long)blockIdx.x*blockDim.x + threadIdx.x;
    long wid = gtid >> 5;
    int lane = (int)(gtid & 31);
    if (wid >= (long)T_*NV) return;
    long tn = wid;
    int t = (int)(tn / NV);
    int c = com[tn];
    float4 mi = *(const float4*)(x + tn*DG + lane*4);
    float4 me = *(const float4*)(meso + ((long)t*CC+c)*DG + lane*4);
    float4 ma = *(const float4*)(mac + (long)t*DG + lane*4);
    float s0 = mi.x+mi.y+mi.z+mi.w;
    float s1 = me.x+me.y+me.z+me.w;
    float s2 = ma.x+ma.y+ma.z+ma.w;
    #pragma unroll
    for (int o=16;o>0;o>>=1){
        s0 += __shfl_xor_sync(0xffffffffu, s0, o);
        s1 += __shfl_xor_sync(0xffffffffu, s1, o);
        s2 += __shfl_xor_sync(0xffffffffu, s2, o);
    }
    s0 *= (1.f/DG); s1 *= (1.f/DG); s2 *= (1.f/DG);
    s0 = (s0>0.f)?s0:0.2f*s0;
    s1 = (s1>0.f)?s1:0.2f*s1;
    s2 = (s2>0.f)?s2:0.2f*s2;
    float mx = fmaxf(s0, fmaxf(s1, s2));
    float e0 = __expf(s0-mx), e1 = __expf(s1-mx), e2 = __expf(s2-mx);
    float inv = __fdividef(1.f, e0+e1+e2);
    float a0 = e0*inv, a1 = e1*inv, a2 = e2*inv;
    float* ap = agg + tn*DAGG + lane*4;
    *(float4*)(ap)        = make_float4(a0*mi.x, a0*mi.y, a0*mi.z, a0*mi.w);
    *(float4*)(ap + DG)   = make_float4(a1*me.x, a1*me.y, a1*me.z, a1*me.w);
    *(float4*)(ap + 2*DG) = make_float4(a2*ma.x, a2*ma.y, a2*ma.z, a2*ma.w);
}

// ---------------- LSTM ----------------
__global__ void lstm_gate(const float* __restrict__ z, float* __restrict__ hs,
                          float* __restrict__ cs)
{
    long idx = (long)blockIdx.x*blockDim.x + threadIdx.x;
    if (idx >= (long)NV*DR) return;
    long n = idx / DR;
    int j = (int)(idx % DR);
    const float* zp = z + n*4*DR;
    float zi = zp[j], zf = zp[DR+j], zg = zp[2*DR+j], zo = zp[3*DR+j];
    float c = fsig(zf)*cs[idx] + fsig(zi)*ftanh(zg);
    cs[idx] = c;
    hs[idx] = fsig(zo)*ftanh(c);
}

// ---------------- decoder normalization ----------------
__global__ void colnorm_k(const float* __restrict__ emb, float* __restrict__ cni){
    int col = blockIdx.x;   // 64
    __shared__ float red[256];
    float s = 0.f;
    for (int n = threadIdx.x; n < NV; n += 256){
        float v = emb[(long)n*DD2 + col];
        s += v*v;
    }
    red[threadIdx.x] = s;
    __syncthreads();
    for (int o=128;o>0;o>>=1){
        if (threadIdx.x < o) red[threadIdx.x] += red[threadIdx.x+o];
        __syncthreads();
    }
    if (threadIdx.x == 0) cni[col] = 1.f / fmaxf(sqrtf(red[0]), 1e-12f);
}

__global__ void norm_sq(const float* __restrict__ emb, const float* __restrict__ cni,
                        float* __restrict__ embn, float* __restrict__ sq)
{
    long gtid = (long)blockIdx.x*blockDim.x + threadIdx.x;
    long row = gtid >> 5;
    int lane = (int)(gtid & 31);
    if (row >= NV) return;
    float a = emb[row*DD2 + lane]      * cni[lane];
    float b = emb[row*DD2 + 32 + lane] * cni[32 + lane];
    embn[row*DD2 + lane] = a;
    embn[row*DD2 + 32 + lane] = b;
    float s = a*a + b*b;
    #pragma unroll
    for (int o=16;o>0;o>>=1) s += __shfl_xor_sync(0xffffffffu, s, o);
    if (lane == 0) sq[row] = s;
}

// ---------------- adjacency: dual tf32 gram + exp epilogue ----------------
// 1 + tanh(-d*s) == 2 / (1 + exp(2*d*s)); __expf overflow/underflow give exact limits.
#define ALD 68
#define BLD 136
__global__ void __launch_bounds__(256) adj_tc(
    const float* __restrict__ embn, const float* __restrict__ scal,
    const float* __restrict__ sq, float* __restrict__ out)
{
    extern __shared__ unsigned smu[];
    unsigned* AE = smu;                    // [128][ALD]
    unsigned* AS = AE + 128*ALD;
    unsigned* BE = AS + 128*ALD;           // [64][BLD] (k-major)
    unsigned* BS = BE + 64*BLD;
    float* sqI = (float*)(BS + 64*BLD);    // [128]
    float* sqJ = sqI + 128;

    const int bi = blockIdx.y, bj = blockIdx.x, tid = threadIdx.x;
    const int wid = tid >> 5, lane = tid & 31;
    const int wm = wid >> 1, wn = wid & 1;
    const int gID = lane >> 2, tig = lane & 3;

    for (int i = tid; i < 128*16; i += 256){
        int r = i >> 4, c4 = (i & 15) * 4;
        float4 v = *(const float4*)(embn + ((long)(bi*128+r))*DD2 + c4);
        unsigned* p = &AE[r*ALD + c4];
        p[0]=f2tf(v.x); p[1]=f2tf(v.y); p[2]=f2tf(v.z); p[3]=f2tf(v.w);
        v = *(const float4*)(scal + ((long)(bi*128+r))*DD2 + c4);
        p = &AS[r*ALD + c4];
        p[0]=f2tf(v.x); p[1]=f2tf(v.y); p[2]=f2tf(v.z); p[3]=f2tf(v.w);
    }
    for (int i = tid; i < 128*16; i += 256){
        int n = i & 127, c4 = (i >> 7) * 4;
        float4 v = *(const float4*)(embn + ((long)(bj*128+n))*DD2 + c4);
        BE[(c4+0)*BLD+n]=f2tf(v.x); BE[(c4+1)*BLD+n]=f2tf(v.y);
        BE[(c4+2)*BLD+n]=f2tf(v.z); BE[(c4+3)*BLD+n]=f2tf(v.w);
        v = *(const float4*)(scal + ((long)(bj*128+n))*DD2 + c4);
        BS[(c4+0)*BLD+n]=f2tf(v.x); BS[(c4+1)*BLD+n]=f2tf(v.y);
        BS[(c4+2)*BLD+n]=f2tf(v.z); BS[(c4+3)*BLD+n]=f2tf(v.w);
    }
    if (tid < 128){ sqI[tid] = sq[bi*128+tid]; sqJ[tid] = sq[bj*128+tid]; }
    __syncthreads();

    float cd[2][8][4], cs[2][8][4];
    #pragma unroll
    for (int i=0;i<2;i++)
        #pragma unroll
        for (int j=0;j<8;j++)
            #pragma unroll
            for (int q=0;q<4;q++){ cd[i][j][q]=0.f; cs[i][j][q]=0.f; }

    #pragma unroll
    for (int ks = 0; ks < 8; ks++){
        const int k = ks*8;
        unsigned aE[2][4], aS[2][4];
        #pragma unroll
        for (int mf=0; mf<2; mf++){
            int bm = wm*32 + mf*16;
            aE[mf][0] = AE[(bm+gID  )*ALD + k + tig];
            aE[mf][1] = AE[(bm+gID+8)*ALD + k + tig];
            aE[mf][2] = AE[(bm+gID  )*ALD + k + tig + 4];
            aE[mf][3] = AE[(bm+gID+8)*ALD + k + tig + 4];
            aS[mf][0] = AS[(bm+gID  )*ALD + k + tig];
            aS[mf][1] = AS[(bm+gID+8)*ALD + k + tig];
            aS[mf][2] = AS[(bm+gID  )*ALD + k + tig + 4];
            aS[mf][3] = AS[(bm+gID+8)*ALD + k + tig + 4];
        }
        unsigned bE[8][2], bS[8][2];
        #pragma unroll
        for (int nf=0; nf<8; nf++){
            int bnn = wn*64 + nf*8;
            bE[nf][0] = BE[(k+tig  )*BLD + bnn + gID];
            bE[nf][1] = BE[(k+tig+4)*BLD + bnn + gID];
            bS[nf][0] = BS[(k+tig  )*BLD + bnn + gID];
            bS[nf][1] = BS[(k+tig+4)*BLD + bnn + gID];
        }
        #pragma unroll
        for (int mf=0; mf<2; mf++)
            #pragma unroll
            for (int nf=0; nf<8; nf++){
                mma_tf32(cd[mf][nf], aE[mf], bE[nf]);
                mma_tf32(cs[mf][nf], aS[mf], bS[nf]);
            }
    }

    #pragma unroll
    for (int mf=0; mf<2; mf++){
        int rl0 = wm*32 + mf*16 + gID;
        #pragma unroll
        for (int nf=0; nf<8; nf++){
            int cl = wn*64 + nf*8 + tig*2;
            #pragma unroll
            for (int half=0; half<2; half++){
                int rl = rl0 + half*8;
                float sqi = sqI[rl];
                float d0 = sqi + sqJ[cl]   - 2.f*cd[mf][nf][half*2+0];
                float d1 = sqi + sqJ[cl+1] - 2.f*cd[mf][nf][half*2+1];
                float v0 = __fdividef(2.f, 1.f + __expf(2.f*d0*cs[mf][nf][half*2+0]));
                float v1 = __fdividef(2.f, 1.f + __expf(2.f*d1*cs[mf][nf][half*2+1]));
                *(float2*)(out + ((long)(bi*128+rl))*NV + bj*128 + cl) = make_float2(v0, v1);
            }
        }
    }
}

// ---------------- launch ----------------
static inline unsigned nb(long n, int b){ return (unsigned)((n + b - 1) / b); }

extern "C" void kernel_launch(void* const* d_in, const int* in_sizes, int n_in,
                              void* d_out, int out_size)
{
    (void)in_sizes; (void)n_in; (void)out_size;
    const int*   ei   = (const int*)  d_in[0];
    const float* ew   = (const float*)d_in[1];
    const float* feat = (const float*)d_in[2];
    const int*   com  = (const int*)  d_in[3];
    const float* nw   = (const float*)d_in[4];
    const float* gatW = (const float*)d_in[5];
    const float* asrc = (const float*)d_in[6];
    const float* adst = (const float*)d_in[7];
    const float* lWx  = (const float*)d_in[8];
    const float* lWh  = (const float*)d_in[9];
    const float* lb   = (const float*)d_in[10];
    const float* eW0  = (const float*)d_in[11];
    const float* eb0  = (const float*)d_in[12];
    const float* eW1  = (const float*)d_in[13];
    const float* eb1  = (const float*)d_in[14];
    const float* sW0  = (const float*)d_in[15];
    const float* sb0  = (const float*)d_in[16];
    const float* sW1  = (const float*)d_in[17];
    const float* sb1  = (const float*)d_in[18];
    float* out = (float*)d_out;

    float* buf = nullptr;
    cudaGetSymbolAddress((void**)&buf, g_buf);
    float* bH   = buf + OFF_H;
    float* bX   = buf + OFF_X;
    float* bSS  = buf + OFF_SS;
    float* bSD  = buf + OFF_SD;
    float* bE   = buf + OFF_E;
    float* bDN  = buf + OFF_DN;
    float* bO   = buf + OFF_O;
    float* bNUM = buf + OFF_NUM;
    float* bCD  = buf + OFF_CD;
    float* bMES = buf + OFF_MES;
    float* bMAC = buf + OFF_MAC;
    float* bAGG = buf + OFF_AGG;
    float* bZX  = buf + OFF_ZX;
    float* bHS  = buf + OFF_HS;
    float* bCS  = buf + OFF_CS;
    float* bE1  = buf + OFF_E1;
    float* bEMB = buf + OFF_EMB;
    float* bEMBN= buf + OFF_EMBN;
    float* bS1  = buf + OFF_S1;
    float* bSC  = buf + OFF_SC;
    float* bSQ  = buf + OFF_SQ;
    float* bCNI = buf + OFF_CNI;

    // -------- GAT layers --------
    const float* xin = feat;
    for (int l = 0; l < 2; l++){
        gemm_tf32<<<dim3(DG/128, (T_*NV)/128), 256>>>(xin, gatW + (long)l*DG*DG, nullptr,
                                                      bH, T_*NV, DG, DG, 0, 0);
        gat_scores<<<nb((long)T_*NV*HH, 256), 256>>>(bH, asrc + l*HH*DHD, adst + l*HH*DHD,
                                                     bSS, bSD);
        fillk<<<nb((long)T_*NV*(HH+DG), 256), 256>>>(bDN, (long)T_*NV*(HH+DG), 0.f);
        edge_softmax<<<nb((long)T_*EE, 256), 256>>>(ei, ew, bSS, bSD, bE, bDN);
        edge_agg<<<nb((long)T_*EE*32, 256), 256>>>(ei, bE, bDN, bH, bO);
        elu_k<<<nb((long)T_*NV*DG, 256), 256>>>(bO, bX, (long)T_*NV*DG);
        xin = bX;
    }

    // -------- hierarchical fuse --------
    fillk<<<nb((long)T_*CC*(DG+1), 256), 256>>>(bNUM, (long)T_*CC*(DG+1), 0.f);
    fuse_pool<<<nb((long)T_*NV*32, 256), 256>>>(bX, com, nw, bNUM, bCD);
    fuse_finalize<<<T_, 128>>>(bNUM, bCD, bMES, bMAC);
    fuse_mix<<<nb((long)T_*NV*32, 256), 256>>>(bX, com, bMES, bMAC, bAGG);

    // -------- LSTM --------
    gemm_tf32<<<dim3((4*DR)/128, (T_*NV)/128), 256>>>(bAGG, lWx, lb, bZX,
                                                      T_*NV, 4*DR, DAGG, 0, 0);
    fillk<<<nb((long)2*NV*DR, 256), 256>>>(bHS, (long)2*NV*DR, 0.f);
    for (int t = 0; t < T_; t++){
        float* zt = bZX + (long)t*NV*4*DR;
        gemm_tf32<<<dim3((4*DR)/128, NV/128), 256>>>(bHS, lWh, nullptr, zt,
                                                     NV, 4*DR, DR, 1, 0);
        lstm_gate<<<nb((long)NV*DR, 256), 256>>>(zt, bHS, bCS);
    }

    // -------- decoders --------
    gemm_tf32<<<dim3(DD1/128, NV/128), 256>>>(bHS, eW0, eb0, bE1, NV, DD1, DR, 0, 1);
    small_gemm<<<nb((long)NV*DD2, 256), 256>>>(bE1, eW1, eb1, bEMB, NV, DD2, DD1, 1);
    gemm_tf32<<<dim3(DD1/128, NV/128), 256>>>(bHS, sW0, sb0, bS1, NV, DD1, DR, 0, 2);
    small_gemm<<<nb((long)NV*DD2, 256), 256>>>(bS1, sW1, sb1, bSC, NV, DD2, DD1, 2);

    colnorm_k<<<DD2, 256>>>(bEMB, bCNI);
    norm_sq<<<nb((long)NV*32, 256), 256>>>(bEMB, bCNI, bEMBN, bSQ);

    // -------- adjacency + emb output --------
    static const int adj_smem = (2*128*ALD + 2*64*BLD + 256) * (int)sizeof(unsigned);
    cudaFuncSetAttribute(adj_tc, cudaFuncAttributeMaxDynamicSharedMemorySize, adj_smem);
    adj_tc<<<dim3(NV/128, NV/128), 256, adj_smem>>>(bEMBN, bSC, bSQ, out);
    copyk<<<nb((long)NV*DD2, 256), 256>>>(bEMB, out + (long)NV*NV, (long)NV*DD2);
}